// round 3
// baseline (speedup 1.0000x reference)
#include <cuda_runtime.h>
#include <math.h>

#define EMB   768
#define NQKV  2304
#define BATCH 4
#define SEQ   2048
#define HEADS 12
#define HDIM  64
#define MTOK  (BATCH*SEQ)     // 8192
#define BH    (BATCH*HEADS)   // 48
#define ATT_SCALE 0.03608439182435161f   // 1/sqrt(768)

// ---------------- device scratch ----------------
__device__ float g_q[(size_t)BH * SEQ * HDIM];
__device__ float g_k[(size_t)BH * SEQ * HDIM];
__device__ float g_v[(size_t)BH * SEQ * HDIM];
__device__ float g_att[(size_t)MTOK * EMB];   // [b*n, h*64+d]

// ================= naive QKV GEMM + split =================
// One thread per output element (m, c) of [8192, 2304].
// qkv[m][c] = sum_k x[m][k] * W_qkv[k][c] + b_qkv[c]
// Decode c = h*192 + d*3 + which  (qkv innermost, per reference reshape)
// and write to q/k/v in [b, h, n, d] layout.
__global__ __launch_bounds__(256) void qkv_naive_kernel(
    const float* __restrict__ x,
    const float* __restrict__ Wq,
    const float* __restrict__ bq)
{
    long long idx = (long long)blockIdx.x * blockDim.x + threadIdx.x;
    if (idx >= (long long)MTOK * NQKV) return;

    int m = (int)(idx / NQKV);     // token index: b*2048 + n
    int c = (int)(idx % NQKV);     // qkv column

    const float* xrow = x + (size_t)m * EMB;
    float s = bq[c];
    for (int k = 0; k < EMB; ++k)
        s = fmaf(xrow[k], Wq[(size_t)k * NQKV + c], s);

    int which = c % 3;             // 0=q, 1=k, 2=v   (innermost)
    int d     = (c / 3) % HDIM;    // head dim
    int h     = c / (HDIM * 3);    // head
    int b     = m / SEQ;
    int n     = m % SEQ;

    float* dst = (which == 0) ? g_q : ((which == 1) ? g_k : g_v);
    dst[(((size_t)b * HEADS + h) * SEQ + n) * HDIM + d] = s;
}

// ================= naive attention (two-pass softmax) =================
// Block = (bh, tile of 128 query rows), 128 threads, one query row per thread.
// Pass A: global max of scores.  Pass B: exp-sum and V accumulation.
__global__ __launch_bounds__(128) void attn_naive_kernel()
{
    __shared__ float Ks[64 * HDIM];   // 64 keys x 64 dims
    __shared__ float Vs[64 * HDIM];

    const int bh  = blockIdx.x;            // b*12 + h
    const int tid = threadIdx.x;
    const int n   = blockIdx.y * 128 + tid;

    const float* Kbase = g_k + (size_t)bh * SEQ * HDIM;
    const float* Vbase = g_v + (size_t)bh * SEQ * HDIM;
    const float* qp    = g_q + ((size_t)bh * SEQ + n) * HDIM;

    float q[HDIM];
#pragma unroll
    for (int d = 0; d < HDIM; ++d) q[d] = qp[d] * ATT_SCALE;

    // ---- pass A: row max ----
    float mmax = -1e30f;
    for (int t0 = 0; t0 < SEQ; t0 += 64) {
        __syncthreads();   // protect previous tile reads
        for (int i = tid; i < 64 * HDIM; i += 128)
            Ks[i] = Kbase[(size_t)t0 * HDIM + i];
        __syncthreads();
        for (int j = 0; j < 64; ++j) {
            float s = 0.0f;
#pragma unroll
            for (int d = 0; d < HDIM; ++d)
                s = fmaf(q[d], Ks[j * HDIM + d], s);
            mmax = fmaxf(mmax, s);
        }
    }

    // ---- pass B: exp-sum + PV accumulation ----
    float l = 0.0f;
    float acc[HDIM];
#pragma unroll
    for (int d = 0; d < HDIM; ++d) acc[d] = 0.0f;

    for (int t0 = 0; t0 < SEQ; t0 += 64) {
        __syncthreads();
        for (int i = tid; i < 64 * HDIM; i += 128) {
            Ks[i] = Kbase[(size_t)t0 * HDIM + i];
            Vs[i] = Vbase[(size_t)t0 * HDIM + i];
        }
        __syncthreads();
        for (int j = 0; j < 64; ++j) {
            float s = 0.0f;
#pragma unroll
            for (int d = 0; d < HDIM; ++d)
                s = fmaf(q[d], Ks[j * HDIM + d], s);
            float p = __expf(s - mmax);
            l += p;
#pragma unroll
            for (int d = 0; d < HDIM; ++d)
                acc[d] = fmaf(p, Vs[j * HDIM + d], acc[d]);
        }
    }

    const float inv = 1.0f / l;
    const int b = bh / HEADS;
    const int h = bh % HEADS;
    float* op = g_att + ((size_t)(b * SEQ + n)) * EMB + h * HDIM;
#pragma unroll
    for (int d = 0; d < HDIM; ++d) op[d] = acc[d] * inv;
}

// ================= naive output projection =================
// One thread per output element (m, c) of [8192, 768].
__global__ __launch_bounds__(256) void proj_naive_kernel(
    const float* __restrict__ Wp,
    const float* __restrict__ bp,
    float* __restrict__ out)
{
    long long idx = (long long)blockIdx.x * blockDim.x + threadIdx.x;
    if (idx >= (long long)MTOK * EMB) return;

    int m = (int)(idx / EMB);
    int c = (int)(idx % EMB);

    const float* arow = g_att + (size_t)m * EMB;
    float s = bp[c];
    for (int k = 0; k < EMB; ++k)
        s = fmaf(arow[k], Wp[(size_t)k * EMB + c], s);

    out[(size_t)m * EMB + c] = s;
}

// ================= launch =================
extern "C" void kernel_launch(void* const* d_in, const int* in_sizes, int n_in,
                              void* d_out, int out_size)
{
    // Identify inputs by element count (all five are pairwise distinct):
    //   x: 6291456, W_qkv: 1769472, b_qkv: 2304, W_proj: 589824, b_proj: 768
    const float *x = nullptr, *Wqkv = nullptr, *bqkv = nullptr,
                *Wproj = nullptr, *bproj = nullptr;
    for (int i = 0; i < n_in; ++i) {
        switch (in_sizes[i]) {
            case 6291456: x     = (const float*)d_in[i]; break;
            case 1769472: Wqkv  = (const float*)d_in[i]; break;
            case 2304:    bqkv  = (const float*)d_in[i]; break;
            case 589824:  Wproj = (const float*)d_in[i]; break;
            case 768:     bproj = (const float*)d_in[i]; break;
            default: break;
        }
    }
    float* out = (float*)d_out;

    {
        long long total = (long long)MTOK * NQKV;
        int blocks = (int)((total + 255) / 256);
        qkv_naive_kernel<<<blocks, 256>>>(x, Wqkv, bqkv);
    }

    attn_naive_kernel<<<dim3(BH, SEQ / 128), 128>>>();

    {
        long long total = (long long)MTOK * EMB;
        int blocks = (int)((total + 255) / 256);
        proj_naive_kernel<<<blocks, 256>>>(Wproj, bproj, out);
    }

    (void)out_size;
}

// round 5
// speedup vs baseline: 1.7831x; 1.7831x over previous
#include <cuda_runtime.h>
#include <math.h>

#define EMB   768
#define NQKV  2304
#define BATCH 4
#define SEQ   2048
#define HEADS 12
#define HDIM  64
#define MTOK  (BATCH*SEQ)     // 8192
#define BH    (BATCH*HEADS)   // 48
#define ATT_SCALE 0.03608439182435161f   // 1/sqrt(768)

// ---------------- device scratch ----------------
__device__ float g_q[(size_t)BH * SEQ * HDIM];
__device__ float g_k[(size_t)BH * SEQ * HDIM];
__device__ float g_v[(size_t)BH * SEQ * HDIM];
__device__ float g_att[(size_t)MTOK * EMB];   // [b*n, h*64+d]

// ================= QKV GEMM, 4 rows x 4 cols per thread =================
// Same element formula as the PROVEN naive kernel:
//   qkv[m][c] = sum_k x[m][k] * W_qkv[k][c] + b_qkv[c]
//   which = c%3, d = (c/3)%64, h = c/192  -> g_q/g_k/g_v [b,h,n,d]
// Thread layout: idx = mg*576 + c4 ; m = mg*4+i, c = c4*4+j.
// 576 % 32 == 0 -> each warp has one m-group (x loads broadcast, W loads coalesced).
__global__ __launch_bounds__(256) void qkv_m4c4_kernel(
    const float* __restrict__ x,
    const float* __restrict__ Wq,
    const float* __restrict__ bq)
{
    const int idx = blockIdx.x * 256 + threadIdx.x;   // 0 .. 2048*576-1
    const int mg  = idx / 576;
    const int c4  = idx % 576;
    const int m0  = mg * 4;
    const int c0  = c4 * 4;

    const float* xr = x + (size_t)m0 * EMB;

    float acc[4][4];
#pragma unroll
    for (int i = 0; i < 4; ++i)
#pragma unroll
        for (int j = 0; j < 4; ++j) acc[i][j] = 0.0f;

#pragma unroll 4
    for (int k = 0; k < EMB; ++k) {
        const float4 w = *(const float4*)&Wq[(size_t)k * NQKV + c0];
        const float x0 = xr[k];
        const float x1 = xr[EMB + k];
        const float x2 = xr[2 * EMB + k];
        const float x3 = xr[3 * EMB + k];
        acc[0][0] = fmaf(x0, w.x, acc[0][0]);
        acc[0][1] = fmaf(x0, w.y, acc[0][1]);
        acc[0][2] = fmaf(x0, w.z, acc[0][2]);
        acc[0][3] = fmaf(x0, w.w, acc[0][3]);
        acc[1][0] = fmaf(x1, w.x, acc[1][0]);
        acc[1][1] = fmaf(x1, w.y, acc[1][1]);
        acc[1][2] = fmaf(x1, w.z, acc[1][2]);
        acc[1][3] = fmaf(x1, w.w, acc[1][3]);
        acc[2][0] = fmaf(x2, w.x, acc[2][0]);
        acc[2][1] = fmaf(x2, w.y, acc[2][1]);
        acc[2][2] = fmaf(x2, w.z, acc[2][2]);
        acc[2][3] = fmaf(x2, w.w, acc[2][3]);
        acc[3][0] = fmaf(x3, w.x, acc[3][0]);
        acc[3][1] = fmaf(x3, w.y, acc[3][1]);
        acc[3][2] = fmaf(x3, w.z, acc[3][2]);
        acc[3][3] = fmaf(x3, w.w, acc[3][3]);
    }

#pragma unroll
    for (int i = 0; i < 4; ++i) {
        const int m = m0 + i;
        const int b = m / SEQ;
        const int n = m % SEQ;
#pragma unroll
        for (int j = 0; j < 4; ++j) {
            const int c = c0 + j;
            const float s = acc[i][j] + bq[c];
            const int which = c % 3;               // 0=q, 1=k, 2=v (innermost)
            const int d     = (c / 3) % HDIM;
            const int h     = c / (HDIM * 3);
            float* dst = (which == 0) ? g_q : ((which == 1) ? g_k : g_v);
            dst[(((size_t)b * HEADS + h) * SEQ + n) * HDIM + d] = s;
        }
    }
}

// ================= attention: PROVEN R3 kernel, verbatim =================
__global__ __launch_bounds__(128) void attn_naive_kernel()
{
    __shared__ float Ks[64 * HDIM];
    __shared__ float Vs[64 * HDIM];

    const int bh  = blockIdx.x;            // b*12 + h
    const int tid = threadIdx.x;
    const int n   = blockIdx.y * 128 + tid;

    const float* Kbase = g_k + (size_t)bh * SEQ * HDIM;
    const float* Vbase = g_v + (size_t)bh * SEQ * HDIM;
    const float* qp    = g_q + ((size_t)bh * SEQ + n) * HDIM;

    float q[HDIM];
#pragma unroll
    for (int d = 0; d < HDIM; ++d) q[d] = qp[d] * ATT_SCALE;

    // ---- pass A: row max ----
    float mmax = -1e30f;
    for (int t0 = 0; t0 < SEQ; t0 += 64) {
        __syncthreads();
        for (int i = tid; i < 64 * HDIM; i += 128)
            Ks[i] = Kbase[(size_t)t0 * HDIM + i];
        __syncthreads();
        for (int j = 0; j < 64; ++j) {
            float s = 0.0f;
#pragma unroll
            for (int d = 0; d < HDIM; ++d)
                s = fmaf(q[d], Ks[j * HDIM + d], s);
            mmax = fmaxf(mmax, s);
        }
    }

    // ---- pass B: exp-sum + PV accumulation ----
    float l = 0.0f;
    float acc[HDIM];
#pragma unroll
    for (int d = 0; d < HDIM; ++d) acc[d] = 0.0f;

    for (int t0 = 0; t0 < SEQ; t0 += 64) {
        __syncthreads();
        for (int i = tid; i < 64 * HDIM; i += 128) {
            Ks[i] = Kbase[(size_t)t0 * HDIM + i];
            Vs[i] = Vbase[(size_t)t0 * HDIM + i];
        }
        __syncthreads();
        for (int j = 0; j < 64; ++j) {
            float s = 0.0f;
#pragma unroll
            for (int d = 0; d < HDIM; ++d)
                s = fmaf(q[d], Ks[j * HDIM + d], s);
            float p = __expf(s - mmax);
            l += p;
#pragma unroll
            for (int d = 0; d < HDIM; ++d)
                acc[d] = fmaf(p, Vs[j * HDIM + d], acc[d]);
        }
    }

    const float inv = 1.0f / l;
    const int b = bh / HEADS;
    const int h = bh % HEADS;
    float* op = g_att + ((size_t)(b * SEQ + n)) * EMB + h * HDIM;
#pragma unroll
    for (int d = 0; d < HDIM; ++d) op[d] = acc[d] * inv;
}

// ================= output projection, 4 rows x 4 cols per thread =================
// out[m][c] = sum_k g_att[m][k] * W_proj[k][c] + b_proj[c]
// idx = mg*192 + c4 ; 192 % 32 == 0 -> warp-uniform m-group.
__global__ __launch_bounds__(256) void proj_m4c4_kernel(
    const float* __restrict__ Wp,
    const float* __restrict__ bp,
    float* __restrict__ out)
{
    const int idx = blockIdx.x * 256 + threadIdx.x;   // 0 .. 2048*192-1
    const int mg  = idx / 192;
    const int c4  = idx % 192;
    const int m0  = mg * 4;
    const int c0  = c4 * 4;

    const float* ar = g_att + (size_t)m0 * EMB;

    float acc[4][4];
#pragma unroll
    for (int i = 0; i < 4; ++i)
#pragma unroll
        for (int j = 0; j < 4; ++j) acc[i][j] = 0.0f;

#pragma unroll 4
    for (int k = 0; k < EMB; ++k) {
        const float4 w = *(const float4*)&Wp[(size_t)k * EMB + c0];
        const float a0 = ar[k];
        const float a1 = ar[EMB + k];
        const float a2 = ar[2 * EMB + k];
        const float a3 = ar[3 * EMB + k];
        acc[0][0] = fmaf(a0, w.x, acc[0][0]);
        acc[0][1] = fmaf(a0, w.y, acc[0][1]);
        acc[0][2] = fmaf(a0, w.z, acc[0][2]);
        acc[0][3] = fmaf(a0, w.w, acc[0][3]);
        acc[1][0] = fmaf(a1, w.x, acc[1][0]);
        acc[1][1] = fmaf(a1, w.y, acc[1][1]);
        acc[1][2] = fmaf(a1, w.z, acc[1][2]);
        acc[1][3] = fmaf(a1, w.w, acc[1][3]);
        acc[2][0] = fmaf(a2, w.x, acc[2][0]);
        acc[2][1] = fmaf(a2, w.y, acc[2][1]);
        acc[2][2] = fmaf(a2, w.z, acc[2][2]);
        acc[2][3] = fmaf(a2, w.w, acc[2][3]);
        acc[3][0] = fmaf(a3, w.x, acc[3][0]);
        acc[3][1] = fmaf(a3, w.y, acc[3][1]);
        acc[3][2] = fmaf(a3, w.z, acc[3][2]);
        acc[3][3] = fmaf(a3, w.w, acc[3][3]);
    }

#pragma unroll
    for (int i = 0; i < 4; ++i) {
        const int m = m0 + i;
#pragma unroll
        for (int j = 0; j < 4; ++j) {
            const int c = c0 + j;
            out[(size_t)m * EMB + c] = acc[i][j] + bp[c];
        }
    }
}

// ================= launch =================
extern "C" void kernel_launch(void* const* d_in, const int* in_sizes, int n_in,
                              void* d_out, int out_size)
{
    // Identify inputs by element count (pairwise distinct; proven in R3):
    //   x: 6291456, W_qkv: 1769472, b_qkv: 2304, W_proj: 589824, b_proj: 768
    const float *x = nullptr, *Wqkv = nullptr, *bqkv = nullptr,
                *Wproj = nullptr, *bproj = nullptr;
    for (int i = 0; i < n_in; ++i) {
        switch (in_sizes[i]) {
            case 6291456: x     = (const float*)d_in[i]; break;
            case 1769472: Wqkv  = (const float*)d_in[i]; break;
            case 2304:    bqkv  = (const float*)d_in[i]; break;
            case 589824:  Wproj = (const float*)d_in[i]; break;
            case 768:     bproj = (const float*)d_in[i]; break;
            default: break;
        }
    }
    float* out = (float*)d_out;

    // 1) QKV GEMM + scatter to q/k/v [b,h,n,d]
    //    threads = (8192/4) * (2304/4) = 2048 * 576 ; / 256 = 4608 blocks
    qkv_m4c4_kernel<<<4608, 256>>>(x, Wqkv, bqkv);

    // 2) attention (proven) -> g_att [b, n, (h d)]
    attn_naive_kernel<<<dim3(BH, SEQ / 128), 128>>>();

    // 3) output projection: threads = 2048 * 192 ; / 256 = 1536 blocks
    proj_m4c4_kernel<<<1536, 256>>>(Wproj, bproj, out);

    (void)out_size;
}

// round 6
// speedup vs baseline: 2.4360x; 1.3662x over previous
#include <cuda_runtime.h>
#include <math.h>

#define EMB   768
#define NQKV  2304
#define BATCH 4
#define SEQ   2048
#define HEADS 12
#define HDIM  64
#define MTOK  (BATCH*SEQ)     // 8192
#define BH    (BATCH*HEADS)   // 48
#define ATT_SCALE 0.03608439182435161f   // 1/sqrt(768)

// ---------------- device scratch ----------------
__device__ __align__(16) float g_q[(size_t)BH * SEQ * HDIM];
__device__ __align__(16) float g_k[(size_t)BH * SEQ * HDIM];
__device__ __align__(16) float g_v[(size_t)BH * SEQ * HDIM];
__device__ __align__(16) float g_att[(size_t)MTOK * EMB];   // [b*n, h*64+d]

// ================= QKV GEMM (PROVEN R5, verbatim) =================
__global__ __launch_bounds__(256) void qkv_m4c4_kernel(
    const float* __restrict__ x,
    const float* __restrict__ Wq,
    const float* __restrict__ bq)
{
    const int idx = blockIdx.x * 256 + threadIdx.x;
    const int mg  = idx / 576;
    const int c4  = idx % 576;
    const int m0  = mg * 4;
    const int c0  = c4 * 4;

    const float* xr = x + (size_t)m0 * EMB;

    float acc[4][4];
#pragma unroll
    for (int i = 0; i < 4; ++i)
#pragma unroll
        for (int j = 0; j < 4; ++j) acc[i][j] = 0.0f;

#pragma unroll 4
    for (int k = 0; k < EMB; ++k) {
        const float4 w = *(const float4*)&Wq[(size_t)k * NQKV + c0];
        const float x0 = xr[k];
        const float x1 = xr[EMB + k];
        const float x2 = xr[2 * EMB + k];
        const float x3 = xr[3 * EMB + k];
        acc[0][0] = fmaf(x0, w.x, acc[0][0]);
        acc[0][1] = fmaf(x0, w.y, acc[0][1]);
        acc[0][2] = fmaf(x0, w.z, acc[0][2]);
        acc[0][3] = fmaf(x0, w.w, acc[0][3]);
        acc[1][0] = fmaf(x1, w.x, acc[1][0]);
        acc[1][1] = fmaf(x1, w.y, acc[1][1]);
        acc[1][2] = fmaf(x1, w.z, acc[1][2]);
        acc[1][3] = fmaf(x1, w.w, acc[1][3]);
        acc[2][0] = fmaf(x2, w.x, acc[2][0]);
        acc[2][1] = fmaf(x2, w.y, acc[2][1]);
        acc[2][2] = fmaf(x2, w.z, acc[2][2]);
        acc[2][3] = fmaf(x2, w.w, acc[2][3]);
        acc[3][0] = fmaf(x3, w.x, acc[3][0]);
        acc[3][1] = fmaf(x3, w.y, acc[3][1]);
        acc[3][2] = fmaf(x3, w.z, acc[3][2]);
        acc[3][3] = fmaf(x3, w.w, acc[3][3]);
    }

#pragma unroll
    for (int i = 0; i < 4; ++i) {
        const int m = m0 + i;
        const int b = m / SEQ;
        const int n = m % SEQ;
#pragma unroll
        for (int j = 0; j < 4; ++j) {
            const int c = c0 + j;
            const float s = acc[i][j] + bq[c];
            const int which = c % 3;               // 0=q, 1=k, 2=v (innermost)
            const int d     = (c / 3) % HDIM;
            const int h     = c / (HDIM * 3);
            float* dst = (which == 0) ? g_q : ((which == 1) ? g_k : g_v);
            dst[(((size_t)b * HEADS + h) * SEQ + n) * HDIM + d] = s;
        }
    }
}

// ================= flash attention: single pass, online softmax =================
// grid (48, 16), 128 threads, one query row per thread; 32-key tiles.
__global__ __launch_bounds__(128) void attn_flash_kernel()
{
    __shared__ float Ks[32 * HDIM];   // 8 KB
    __shared__ float Vs[32 * HDIM];   // 8 KB

    const int bh  = blockIdx.x;            // b*12 + h
    const int tid = threadIdx.x;
    const int n   = blockIdx.y * 128 + tid;

    const float4* Kb = (const float4*)(g_k + (size_t)bh * SEQ * HDIM);
    const float4* Vb = (const float4*)(g_v + (size_t)bh * SEQ * HDIM);
    const float*  qp = g_q + ((size_t)bh * SEQ + n) * HDIM;

    float q[HDIM];
#pragma unroll
    for (int d = 0; d < HDIM; d += 4) {
        const float4 t = *(const float4*)(qp + d);
        q[d + 0] = t.x * ATT_SCALE;
        q[d + 1] = t.y * ATT_SCALE;
        q[d + 2] = t.z * ATT_SCALE;
        q[d + 3] = t.w * ATT_SCALE;
    }

    float acc[HDIM];
#pragma unroll
    for (int d = 0; d < HDIM; ++d) acc[d] = 0.0f;
    float mrun = -1e30f;
    float lrun = 0.0f;

    for (int kt = 0; kt < SEQ / 32; ++kt) {
        __syncthreads();   // previous tile fully consumed
#pragma unroll
        for (int u = 0; u < 4; ++u) {
            const int i = u * 128 + tid;   // 512 float4 per 32x64 tile
            ((float4*)Ks)[i] = Kb[kt * 512 + i];
            ((float4*)Vs)[i] = Vb[kt * 512 + i];
        }
        __syncthreads();

        // ---- scores for 32 keys (kept in registers) ----
        float s[32];
        float tmax = -1e30f;
#pragma unroll
        for (int j = 0; j < 32; ++j) {
            const float* kr = Ks + j * HDIM;
            float s0 = 0.0f, s1 = 0.0f, s2 = 0.0f, s3 = 0.0f;
#pragma unroll
            for (int d = 0; d < HDIM; d += 4) {
                const float4 kv = *(const float4*)(kr + d);
                s0 = fmaf(q[d + 0], kv.x, s0);
                s1 = fmaf(q[d + 1], kv.y, s1);
                s2 = fmaf(q[d + 2], kv.z, s2);
                s3 = fmaf(q[d + 3], kv.w, s3);
            }
            s[j] = (s0 + s1) + (s2 + s3);
            tmax = fmaxf(tmax, s[j]);
        }

        // ---- online softmax update ----
        const float mnew = fmaxf(mrun, tmax);
        const float corr = __expf(mrun - mnew);
        lrun *= corr;
#pragma unroll
        for (int d = 0; d < HDIM; ++d) acc[d] *= corr;
        mrun = mnew;

        // ---- probability-weighted V accumulation ----
#pragma unroll
        for (int j = 0; j < 32; ++j) {
            const float p = __expf(s[j] - mnew);
            lrun += p;
            const float* vr = Vs + j * HDIM;
#pragma unroll
            for (int d = 0; d < HDIM; d += 4) {
                const float4 vv = *(const float4*)(vr + d);
                acc[d + 0] = fmaf(p, vv.x, acc[d + 0]);
                acc[d + 1] = fmaf(p, vv.y, acc[d + 1]);
                acc[d + 2] = fmaf(p, vv.z, acc[d + 2]);
                acc[d + 3] = fmaf(p, vv.w, acc[d + 3]);
            }
        }
    }

    const float inv = 1.0f / lrun;
    const int b = bh / HEADS;
    const int h = bh % HEADS;
    float* op = g_att + ((size_t)(b * SEQ + n)) * EMB + h * HDIM;
#pragma unroll
    for (int d = 0; d < HDIM; d += 4) {
        float4 r;
        r.x = acc[d + 0] * inv;
        r.y = acc[d + 1] * inv;
        r.z = acc[d + 2] * inv;
        r.w = acc[d + 3] * inv;
        *(float4*)(op + d) = r;
    }
}

// ================= output projection (PROVEN R5, verbatim) =================
__global__ __launch_bounds__(256) void proj_m4c4_kernel(
    const float* __restrict__ Wp,
    const float* __restrict__ bp,
    float* __restrict__ out)
{
    const int idx = blockIdx.x * 256 + threadIdx.x;
    const int mg  = idx / 192;
    const int c4  = idx % 192;
    const int m0  = mg * 4;
    const int c0  = c4 * 4;

    const float* ar = g_att + (size_t)m0 * EMB;

    float acc[4][4];
#pragma unroll
    for (int i = 0; i < 4; ++i)
#pragma unroll
        for (int j = 0; j < 4; ++j) acc[i][j] = 0.0f;

#pragma unroll 4
    for (int k = 0; k < EMB; ++k) {
        const float4 w = *(const float4*)&Wp[(size_t)k * EMB + c0];
        const float a0 = ar[k];
        const float a1 = ar[EMB + k];
        const float a2 = ar[2 * EMB + k];
        const float a3 = ar[3 * EMB + k];
        acc[0][0] = fmaf(a0, w.x, acc[0][0]);
        acc[0][1] = fmaf(a0, w.y, acc[0][1]);
        acc[0][2] = fmaf(a0, w.z, acc[0][2]);
        acc[0][3] = fmaf(a0, w.w, acc[0][3]);
        acc[1][0] = fmaf(a1, w.x, acc[1][0]);
        acc[1][1] = fmaf(a1, w.y, acc[1][1]);
        acc[1][2] = fmaf(a1, w.z, acc[1][2]);
        acc[1][3] = fmaf(a1, w.w, acc[1][3]);
        acc[2][0] = fmaf(a2, w.x, acc[2][0]);
        acc[2][1] = fmaf(a2, w.y, acc[2][1]);
        acc[2][2] = fmaf(a2, w.z, acc[2][2]);
        acc[2][3] = fmaf(a2, w.w, acc[2][3]);
        acc[3][0] = fmaf(a3, w.x, acc[3][0]);
        acc[3][1] = fmaf(a3, w.y, acc[3][1]);
        acc[3][2] = fmaf(a3, w.z, acc[3][2]);
        acc[3][3] = fmaf(a3, w.w, acc[3][3]);
    }

#pragma unroll
    for (int i = 0; i < 4; ++i) {
        const int m = m0 + i;
#pragma unroll
        for (int j = 0; j < 4; ++j) {
            const int c = c0 + j;
            out[(size_t)m * EMB + c] = acc[i][j] + bp[c];
        }
    }
}

// ================= launch =================
extern "C" void kernel_launch(void* const* d_in, const int* in_sizes, int n_in,
                              void* d_out, int out_size)
{
    const float *x = nullptr, *Wqkv = nullptr, *bqkv = nullptr,
                *Wproj = nullptr, *bproj = nullptr;
    for (int i = 0; i < n_in; ++i) {
        switch (in_sizes[i]) {
            case 6291456: x     = (const float*)d_in[i]; break;
            case 1769472: Wqkv  = (const float*)d_in[i]; break;
            case 2304:    bqkv  = (const float*)d_in[i]; break;
            case 589824:  Wproj = (const float*)d_in[i]; break;
            case 768:     bproj = (const float*)d_in[i]; break;
            default: break;
        }
    }
    float* out = (float*)d_out;

    qkv_m4c4_kernel<<<4608, 256>>>(x, Wqkv, bqkv);
    attn_flash_kernel<<<dim3(BH, SEQ / 128), 128>>>();
    proj_m4c4_kernel<<<1536, 256>>>(Wproj, bproj, out);

    (void)out_size;
}

// round 7
// speedup vs baseline: 2.4632x; 1.0112x over previous
#include <cuda_runtime.h>
#include <math.h>

#define EMB   768
#define NQKV  2304
#define BATCH 4
#define SEQ   2048
#define HEADS 12
#define HDIM  64
#define MTOK  (BATCH*SEQ)     // 8192
#define BH    (BATCH*HEADS)   // 48
#define ATT_SCALE 0.03608439182435161f   // 1/sqrt(768)

// ---------------- device scratch ----------------
__device__ __align__(16) float g_q[(size_t)BH * SEQ * HDIM];
__device__ __align__(16) float g_k[(size_t)BH * SEQ * HDIM];
__device__ __align__(16) float g_v[(size_t)BH * SEQ * HDIM];
__device__ __align__(16) float g_att[(size_t)MTOK * EMB];   // [b*n, h*64+d]

// ================= QKV GEMM, 8 rows x 4 cols per thread, k-quad loads =================
// Element formula identical to proven R5 kernel:
//   qkv[m][c] = sum_k x[m][k]*W_qkv[k][c] + b_qkv[c];  which=c%3, d=(c/3)%64, h=c/192
__global__ __launch_bounds__(256) void qkv_m8c4_kernel(
    const float* __restrict__ x,
    const float* __restrict__ Wq,
    const float* __restrict__ bq)
{
    const int idx = blockIdx.x * 256 + threadIdx.x;   // 0 .. 1024*576-1
    const int mg  = idx / 576;
    const int c4  = idx % 576;
    const int m0  = mg * 8;
    const int c0  = c4 * 4;

    const float* xr = x + (size_t)m0 * EMB;

    float acc[8][4];
#pragma unroll
    for (int i = 0; i < 8; ++i)
#pragma unroll
        for (int j = 0; j < 4; ++j) acc[i][j] = 0.0f;

    for (int k4 = 0; k4 < EMB; k4 += 4) {
        // 4 W rows (k4..k4+3), 4 cols each
        float4 w0 = *(const float4*)&Wq[(size_t)(k4 + 0) * NQKV + c0];
        float4 w1 = *(const float4*)&Wq[(size_t)(k4 + 1) * NQKV + c0];
        float4 w2 = *(const float4*)&Wq[(size_t)(k4 + 2) * NQKV + c0];
        float4 w3 = *(const float4*)&Wq[(size_t)(k4 + 3) * NQKV + c0];

#pragma unroll
        for (int i = 0; i < 8; ++i) {
            const float4 xv = *(const float4*)&xr[(size_t)i * EMB + k4];
            acc[i][0] = fmaf(xv.x, w0.x, acc[i][0]);
            acc[i][1] = fmaf(xv.x, w0.y, acc[i][1]);
            acc[i][2] = fmaf(xv.x, w0.z, acc[i][2]);
            acc[i][3] = fmaf(xv.x, w0.w, acc[i][3]);
            acc[i][0] = fmaf(xv.y, w1.x, acc[i][0]);
            acc[i][1] = fmaf(xv.y, w1.y, acc[i][1]);
            acc[i][2] = fmaf(xv.y, w1.z, acc[i][2]);
            acc[i][3] = fmaf(xv.y, w1.w, acc[i][3]);
            acc[i][0] = fmaf(xv.z, w2.x, acc[i][0]);
            acc[i][1] = fmaf(xv.z, w2.y, acc[i][1]);
            acc[i][2] = fmaf(xv.z, w2.z, acc[i][2]);
            acc[i][3] = fmaf(xv.z, w2.w, acc[i][3]);
            acc[i][0] = fmaf(xv.w, w3.x, acc[i][0]);
            acc[i][1] = fmaf(xv.w, w3.y, acc[i][1]);
            acc[i][2] = fmaf(xv.w, w3.z, acc[i][2]);
            acc[i][3] = fmaf(xv.w, w3.w, acc[i][3]);
        }
    }

#pragma unroll
    for (int i = 0; i < 8; ++i) {
        const int m = m0 + i;
        const int b = m / SEQ;
        const int n = m % SEQ;
#pragma unroll
        for (int j = 0; j < 4; ++j) {
            const int c = c0 + j;
            const float s = acc[i][j] + bq[c];
            const int which = c % 3;               // 0=q, 1=k, 2=v (innermost)
            const int d     = (c / 3) % HDIM;
            const int h     = c / (HDIM * 3);
            float* dst = (which == 0) ? g_q : ((which == 1) ? g_k : g_v);
            dst[(((size_t)b * HEADS + h) * SEQ + n) * HDIM + d] = s;
        }
    }
}

// ================= flash attention (PROVEN R6, verbatim) =================
__global__ __launch_bounds__(128) void attn_flash_kernel()
{
    __shared__ float Ks[32 * HDIM];
    __shared__ float Vs[32 * HDIM];

    const int bh  = blockIdx.x;
    const int tid = threadIdx.x;
    const int n   = blockIdx.y * 128 + tid;

    const float4* Kb = (const float4*)(g_k + (size_t)bh * SEQ * HDIM);
    const float4* Vb = (const float4*)(g_v + (size_t)bh * SEQ * HDIM);
    const float*  qp = g_q + ((size_t)bh * SEQ + n) * HDIM;

    float q[HDIM];
#pragma unroll
    for (int d = 0; d < HDIM; d += 4) {
        const float4 t = *(const float4*)(qp + d);
        q[d + 0] = t.x * ATT_SCALE;
        q[d + 1] = t.y * ATT_SCALE;
        q[d + 2] = t.z * ATT_SCALE;
        q[d + 3] = t.w * ATT_SCALE;
    }

    float acc[HDIM];
#pragma unroll
    for (int d = 0; d < HDIM; ++d) acc[d] = 0.0f;
    float mrun = -1e30f;
    float lrun = 0.0f;

    for (int kt = 0; kt < SEQ / 32; ++kt) {
        __syncthreads();
#pragma unroll
        for (int u = 0; u < 4; ++u) {
            const int i = u * 128 + tid;
            ((float4*)Ks)[i] = Kb[kt * 512 + i];
            ((float4*)Vs)[i] = Vb[kt * 512 + i];
        }
        __syncthreads();

        float s[32];
        float tmax = -1e30f;
#pragma unroll
        for (int j = 0; j < 32; ++j) {
            const float* kr = Ks + j * HDIM;
            float s0 = 0.0f, s1 = 0.0f, s2 = 0.0f, s3 = 0.0f;
#pragma unroll
            for (int d = 0; d < HDIM; d += 4) {
                const float4 kv = *(const float4*)(kr + d);
                s0 = fmaf(q[d + 0], kv.x, s0);
                s1 = fmaf(q[d + 1], kv.y, s1);
                s2 = fmaf(q[d + 2], kv.z, s2);
                s3 = fmaf(q[d + 3], kv.w, s3);
            }
            s[j] = (s0 + s1) + (s2 + s3);
            tmax = fmaxf(tmax, s[j]);
        }

        const float mnew = fmaxf(mrun, tmax);
        const float corr = __expf(mrun - mnew);
        lrun *= corr;
#pragma unroll
        for (int d = 0; d < HDIM; ++d) acc[d] *= corr;
        mrun = mnew;

#pragma unroll
        for (int j = 0; j < 32; ++j) {
            const float p = __expf(s[j] - mnew);
            lrun += p;
            const float* vr = Vs + j * HDIM;
#pragma unroll
            for (int d = 0; d < HDIM; d += 4) {
                const float4 vv = *(const float4*)(vr + d);
                acc[d + 0] = fmaf(p, vv.x, acc[d + 0]);
                acc[d + 1] = fmaf(p, vv.y, acc[d + 1]);
                acc[d + 2] = fmaf(p, vv.z, acc[d + 2]);
                acc[d + 3] = fmaf(p, vv.w, acc[d + 3]);
            }
        }
    }

    const float inv = 1.0f / lrun;
    const int b = bh / HEADS;
    const int h = bh % HEADS;
    float* op = g_att + ((size_t)(b * SEQ + n)) * EMB + h * HDIM;
#pragma unroll
    for (int d = 0; d < HDIM; d += 4) {
        float4 r;
        r.x = acc[d + 0] * inv;
        r.y = acc[d + 1] * inv;
        r.z = acc[d + 2] * inv;
        r.w = acc[d + 3] * inv;
        *(float4*)(op + d) = r;
    }
}

// ================= output projection, 8 rows x 4 cols per thread =================
__global__ __launch_bounds__(256) void proj_m8c4_kernel(
    const float* __restrict__ Wp,
    const float* __restrict__ bp,
    float* __restrict__ out)
{
    const int idx = blockIdx.x * 256 + threadIdx.x;   // 0 .. 1024*192-1
    const int mg  = idx / 192;
    const int c4  = idx % 192;
    const int m0  = mg * 8;
    const int c0  = c4 * 4;

    const float* ar = g_att + (size_t)m0 * EMB;

    float acc[8][4];
#pragma unroll
    for (int i = 0; i < 8; ++i)
#pragma unroll
        for (int j = 0; j < 4; ++j) acc[i][j] = 0.0f;

    for (int k4 = 0; k4 < EMB; k4 += 4) {
        float4 w0 = *(const float4*)&Wp[(size_t)(k4 + 0) * EMB + c0];
        float4 w1 = *(const float4*)&Wp[(size_t)(k4 + 1) * EMB + c0];
        float4 w2 = *(const float4*)&Wp[(size_t)(k4 + 2) * EMB + c0];
        float4 w3 = *(const float4*)&Wp[(size_t)(k4 + 3) * EMB + c0];

#pragma unroll
        for (int i = 0; i < 8; ++i) {
            const float4 av = *(const float4*)&ar[(size_t)i * EMB + k4];
            acc[i][0] = fmaf(av.x, w0.x, acc[i][0]);
            acc[i][1] = fmaf(av.x, w0.y, acc[i][1]);
            acc[i][2] = fmaf(av.x, w0.z, acc[i][2]);
            acc[i][3] = fmaf(av.x, w0.w, acc[i][3]);
            acc[i][0] = fmaf(av.y, w1.x, acc[i][0]);
            acc[i][1] = fmaf(av.y, w1.y, acc[i][1]);
            acc[i][2] = fmaf(av.y, w1.z, acc[i][2]);
            acc[i][3] = fmaf(av.y, w1.w, acc[i][3]);
            acc[i][0] = fmaf(av.z, w2.x, acc[i][0]);
            acc[i][1] = fmaf(av.z, w2.y, acc[i][1]);
            acc[i][2] = fmaf(av.z, w2.z, acc[i][2]);
            acc[i][3] = fmaf(av.z, w2.w, acc[i][3]);
            acc[i][0] = fmaf(av.w, w3.x, acc[i][0]);
            acc[i][1] = fmaf(av.w, w3.y, acc[i][1]);
            acc[i][2] = fmaf(av.w, w3.z, acc[i][2]);
            acc[i][3] = fmaf(av.w, w3.w, acc[i][3]);
        }
    }

#pragma unroll
    for (int i = 0; i < 8; ++i) {
        const int m = m0 + i;
#pragma unroll
        for (int j = 0; j < 4; ++j) {
            const int c = c0 + j;
            out[(size_t)m * EMB + c] = acc[i][j] + bp[c];
        }
    }
}

// ================= launch =================
extern "C" void kernel_launch(void* const* d_in, const int* in_sizes, int n_in,
                              void* d_out, int out_size)
{
    const float *x = nullptr, *Wqkv = nullptr, *bqkv = nullptr,
                *Wproj = nullptr, *bproj = nullptr;
    for (int i = 0; i < n_in; ++i) {
        switch (in_sizes[i]) {
            case 6291456: x     = (const float*)d_in[i]; break;
            case 1769472: Wqkv  = (const float*)d_in[i]; break;
            case 2304:    bqkv  = (const float*)d_in[i]; break;
            case 589824:  Wproj = (const float*)d_in[i]; break;
            case 768:     bproj = (const float*)d_in[i]; break;
            default: break;
        }
    }
    float* out = (float*)d_out;

    // qkv: (8192/8)*(2304/4) = 1024*576 threads -> 2304 blocks
    qkv_m8c4_kernel<<<2304, 256>>>(x, Wqkv, bqkv);
    attn_flash_kernel<<<dim3(BH, SEQ / 128), 128>>>();
    // proj: (8192/8)*(768/4) = 1024*192 threads -> 768 blocks
    proj_m8c4_kernel<<<768, 256>>>(Wproj, bproj, out);

    (void)out_size;
}

// round 8
// speedup vs baseline: 2.6434x; 1.0732x over previous
#include <cuda_runtime.h>
#include <math.h>

#define EMB   768
#define NQKV  2304
#define BATCH 4
#define SEQ   2048
#define HEADS 12
#define HDIM  64
#define MTOK  (BATCH*SEQ)     // 8192
#define BH    (BATCH*HEADS)   // 48
#define ATT_SCALE 0.03608439182435161f   // 1/sqrt(768)

typedef unsigned long long u64t;

// ---- packed f32x2 helpers (Blackwell sm_103a) ----
__device__ __forceinline__ u64t pack2(float lo, float hi) {
    u64t r;
    asm("mov.b64 %0, {%1, %2};" : "=l"(r) : "f"(lo), "f"(hi));
    return r;
}
__device__ __forceinline__ void unpack2(u64t v, float& lo, float& hi) {
    asm("mov.b64 {%0, %1}, %2;" : "=f"(lo), "=f"(hi) : "l"(v));
}
__device__ __forceinline__ u64t fma2(u64t a, u64t b, u64t c) {
    u64t r;
    asm("fma.rn.f32x2 %0, %1, %2, %3;" : "=l"(r) : "l"(a), "l"(b), "l"(c));
    return r;
}
__device__ __forceinline__ u64t mul2(u64t a, u64t b) {
    u64t r;
    asm("mul.rn.f32x2 %0, %1, %2;" : "=l"(r) : "l"(a), "l"(b));
    return r;
}

// ---------------- device scratch ----------------
__device__ __align__(16) float g_q[(size_t)BH * SEQ * HDIM];
__device__ __align__(16) float g_k[(size_t)BH * SEQ * HDIM];
__device__ __align__(16) float g_v[(size_t)BH * SEQ * HDIM];
__device__ __align__(16) float g_att[(size_t)MTOK * EMB];   // [b*n, h*64+d]

// ================= QKV GEMM, 8x4 per thread, FMA2 =================
// Element formula identical to proven R5/R7 kernel:
//   qkv[m][c] = sum_k x[m][k]*W_qkv[k][c] + b_qkv[c];  which=c%3, d=(c/3)%64, h=c/192
__global__ __launch_bounds__(256) void qkv_m8c4_f2_kernel(
    const float* __restrict__ x,
    const float* __restrict__ Wq,
    const float* __restrict__ bq)
{
    const int idx = blockIdx.x * 256 + threadIdx.x;   // 0 .. 1024*576-1
    const int mg  = idx / 576;
    const int c4  = idx % 576;
    const int m0  = mg * 8;
    const int c0  = c4 * 4;

    const float* xr = x + (size_t)m0 * EMB;

    u64t acc2[8][2];   // lanes: [i][0]=(c0,c0+1), [i][1]=(c0+2,c0+3)
#pragma unroll
    for (int i = 0; i < 8; ++i) { acc2[i][0] = 0ull; acc2[i][1] = 0ull; }

#pragma unroll 2
    for (int k4 = 0; k4 < EMB; k4 += 4) {
        const ulonglong2 wv0 = *(const ulonglong2*)&Wq[(size_t)(k4 + 0) * NQKV + c0];
        const ulonglong2 wv1 = *(const ulonglong2*)&Wq[(size_t)(k4 + 1) * NQKV + c0];
        const ulonglong2 wv2 = *(const ulonglong2*)&Wq[(size_t)(k4 + 2) * NQKV + c0];
        const ulonglong2 wv3 = *(const ulonglong2*)&Wq[(size_t)(k4 + 3) * NQKV + c0];

#pragma unroll
        for (int i = 0; i < 8; ++i) {
            const float4 xv = *(const float4*)&xr[(size_t)i * EMB + k4];
            const u64t x0 = pack2(xv.x, xv.x);
            const u64t x1 = pack2(xv.y, xv.y);
            const u64t x2 = pack2(xv.z, xv.z);
            const u64t x3 = pack2(xv.w, xv.w);
            acc2[i][0] = fma2(x0, wv0.x, acc2[i][0]);
            acc2[i][1] = fma2(x0, wv0.y, acc2[i][1]);
            acc2[i][0] = fma2(x1, wv1.x, acc2[i][0]);
            acc2[i][1] = fma2(x1, wv1.y, acc2[i][1]);
            acc2[i][0] = fma2(x2, wv2.x, acc2[i][0]);
            acc2[i][1] = fma2(x2, wv2.y, acc2[i][1]);
            acc2[i][0] = fma2(x3, wv3.x, acc2[i][0]);
            acc2[i][1] = fma2(x3, wv3.y, acc2[i][1]);
        }
    }

#pragma unroll
    for (int i = 0; i < 8; ++i) {
        const int m = m0 + i;
        const int b = m / SEQ;
        const int n = m % SEQ;
        float a[4];
        unpack2(acc2[i][0], a[0], a[1]);
        unpack2(acc2[i][1], a[2], a[3]);
#pragma unroll
        for (int j = 0; j < 4; ++j) {
            const int c = c0 + j;
            const float s = a[j] + bq[c];
            const int which = c % 3;               // 0=q, 1=k, 2=v (innermost)
            const int d     = (c / 3) % HDIM;
            const int h     = c / (HDIM * 3);
            float* dst = (which == 0) ? g_q : ((which == 1) ? g_k : g_v);
            dst[(((size_t)b * HEADS + h) * SEQ + n) * HDIM + d] = s;
        }
    }
}

// ================= flash attention, single pass, FMA2 =================
// Same algorithm as proven R6 kernel; inner products via packed f32x2.
__global__ __launch_bounds__(128) void attn_flash_f2_kernel()
{
    __shared__ float Ks[32 * HDIM];
    __shared__ float Vs[32 * HDIM];

    const int bh  = blockIdx.x;
    const int tid = threadIdx.x;
    const int n   = blockIdx.y * 128 + tid;

    const float4* Kb = (const float4*)(g_k + (size_t)bh * SEQ * HDIM);
    const float4* Vb = (const float4*)(g_v + (size_t)bh * SEQ * HDIM);
    const float*  qp = g_q + ((size_t)bh * SEQ + n) * HDIM;

    // q2[t] = (q[2t], q[2t+1]) * scale
    u64t q2[32];
#pragma unroll
    for (int d = 0; d < HDIM; d += 4) {
        const float4 t = *(const float4*)(qp + d);
        q2[d / 2]     = pack2(t.x * ATT_SCALE, t.y * ATT_SCALE);
        q2[d / 2 + 1] = pack2(t.z * ATT_SCALE, t.w * ATT_SCALE);
    }

    u64t accv[32];   // accv[t] = (acc[2t], acc[2t+1])
#pragma unroll
    for (int t = 0; t < 32; ++t) accv[t] = 0ull;
    float mrun = -1e30f;
    float lrun = 0.0f;

    for (int kt = 0; kt < SEQ / 32; ++kt) {
        __syncthreads();
#pragma unroll
        for (int u = 0; u < 4; ++u) {
            const int i = u * 128 + tid;
            ((float4*)Ks)[i] = Kb[kt * 512 + i];
            ((float4*)Vs)[i] = Vb[kt * 512 + i];
        }
        __syncthreads();

        // ---- scores ----
        float s[32];
        float tmax = -1e30f;
#pragma unroll
        for (int j = 0; j < 32; ++j) {
            const ulonglong2* kr2 = (const ulonglong2*)(Ks + j * HDIM);
            u64t a01 = 0ull, a23 = 0ull;
#pragma unroll
            for (int t = 0; t < 16; ++t) {
                const ulonglong2 kv = kr2[t];
                a01 = fma2(q2[2 * t],     kv.x, a01);
                a23 = fma2(q2[2 * t + 1], kv.y, a23);
            }
            float l0, l1, l2, l3;
            unpack2(a01, l0, l1);
            unpack2(a23, l2, l3);
            s[j] = (l0 + l1) + (l2 + l3);
            tmax = fmaxf(tmax, s[j]);
        }

        // ---- online softmax ----
        const float mnew = fmaxf(mrun, tmax);
        const float corr = __expf(mrun - mnew);
        lrun *= corr;
        const u64t corr2 = pack2(corr, corr);
#pragma unroll
        for (int t = 0; t < 32; ++t) accv[t] = mul2(accv[t], corr2);
        mrun = mnew;

        // ---- PV ----
#pragma unroll
        for (int j = 0; j < 32; ++j) {
            const float p = __expf(s[j] - mnew);
            lrun += p;
            const u64t p2 = pack2(p, p);
            const ulonglong2* vr2 = (const ulonglong2*)(Vs + j * HDIM);
#pragma unroll
            for (int t = 0; t < 16; ++t) {
                const ulonglong2 vv = vr2[t];
                accv[2 * t]     = fma2(p2, vv.x, accv[2 * t]);
                accv[2 * t + 1] = fma2(p2, vv.y, accv[2 * t + 1]);
            }
        }
    }

    const float inv = 1.0f / lrun;
    const int b = bh / HEADS;
    const int h = bh % HEADS;
    float* op = g_att + ((size_t)(b * SEQ + n)) * EMB + h * HDIM;
#pragma unroll
    for (int d = 0; d < HDIM; d += 4) {
        float a0, a1, a2, a3;
        unpack2(accv[d / 2],     a0, a1);
        unpack2(accv[d / 2 + 1], a2, a3);
        float4 r;
        r.x = a0 * inv;
        r.y = a1 * inv;
        r.z = a2 * inv;
        r.w = a3 * inv;
        *(float4*)(op + d) = r;
    }
}

// ================= output projection, 8x4 per thread, FMA2 =================
__global__ __launch_bounds__(256) void proj_m8c4_f2_kernel(
    const float* __restrict__ Wp,
    const float* __restrict__ bp,
    float* __restrict__ out)
{
    const int idx = blockIdx.x * 256 + threadIdx.x;   // 0 .. 1024*192-1
    const int mg  = idx / 192;
    const int c4  = idx % 192;
    const int m0  = mg * 8;
    const int c0  = c4 * 4;

    const float* ar = g_att + (size_t)m0 * EMB;

    u64t acc2[8][2];
#pragma unroll
    for (int i = 0; i < 8; ++i) { acc2[i][0] = 0ull; acc2[i][1] = 0ull; }

#pragma unroll 2
    for (int k4 = 0; k4 < EMB; k4 += 4) {
        const ulonglong2 wv0 = *(const ulonglong2*)&Wp[(size_t)(k4 + 0) * EMB + c0];
        const ulonglong2 wv1 = *(const ulonglong2*)&Wp[(size_t)(k4 + 1) * EMB + c0];
        const ulonglong2 wv2 = *(const ulonglong2*)&Wp[(size_t)(k4 + 2) * EMB + c0];
        const ulonglong2 wv3 = *(const ulonglong2*)&Wp[(size_t)(k4 + 3) * EMB + c0];

#pragma unroll
        for (int i = 0; i < 8; ++i) {
            const float4 av = *(const float4*)&ar[(size_t)i * EMB + k4];
            const u64t a0 = pack2(av.x, av.x);
            const u64t a1 = pack2(av.y, av.y);
            const u64t a2 = pack2(av.z, av.z);
            const u64t a3 = pack2(av.w, av.w);
            acc2[i][0] = fma2(a0, wv0.x, acc2[i][0]);
            acc2[i][1] = fma2(a0, wv0.y, acc2[i][1]);
            acc2[i][0] = fma2(a1, wv1.x, acc2[i][0]);
            acc2[i][1] = fma2(a1, wv1.y, acc2[i][1]);
            acc2[i][0] = fma2(a2, wv2.x, acc2[i][0]);
            acc2[i][1] = fma2(a2, wv2.y, acc2[i][1]);
            acc2[i][0] = fma2(a3, wv3.x, acc2[i][0]);
            acc2[i][1] = fma2(a3, wv3.y, acc2[i][1]);
        }
    }

#pragma unroll
    for (int i = 0; i < 8; ++i) {
        const int m = m0 + i;
        float a[4];
        unpack2(acc2[i][0], a[0], a[1]);
        unpack2(acc2[i][1], a[2], a[3]);
        float4 r;
        r.x = a[0] + bp[c0 + 0];
        r.y = a[1] + bp[c0 + 1];
        r.z = a[2] + bp[c0 + 2];
        r.w = a[3] + bp[c0 + 3];
        *(float4*)(out + (size_t)m * EMB + c0) = r;
    }
}

// ================= launch =================
extern "C" void kernel_launch(void* const* d_in, const int* in_sizes, int n_in,
                              void* d_out, int out_size)
{
    const float *x = nullptr, *Wqkv = nullptr, *bqkv = nullptr,
                *Wproj = nullptr, *bproj = nullptr;
    for (int i = 0; i < n_in; ++i) {
        switch (in_sizes[i]) {
            case 6291456: x     = (const float*)d_in[i]; break;
            case 1769472: Wqkv  = (const float*)d_in[i]; break;
            case 2304:    bqkv  = (const float*)d_in[i]; break;
            case 589824:  Wproj = (const float*)d_in[i]; break;
            case 768:     bproj = (const float*)d_in[i]; break;
            default: break;
        }
    }
    float* out = (float*)d_out;

    // qkv: (8192/8)*(2304/4) = 1024*576 threads -> 2304 blocks
    qkv_m8c4_f2_kernel<<<2304, 256>>>(x, Wqkv, bqkv);
    attn_flash_f2_kernel<<<dim3(BH, SEQ / 128), 128>>>();
    // proj: (8192/8)*(768/4) = 1024*192 threads -> 768 blocks
    proj_m8c4_f2_kernel<<<768, 256>>>(Wproj, bproj, out);

    (void)out_size;
}

// round 10
// speedup vs baseline: 3.1753x; 1.2012x over previous
#include <cuda_runtime.h>
#include <math.h>
#include <stdint.h>

#define EMB   768
#define NQKV  2304
#define BATCH 4
#define SEQ   2048
#define HEADS 12
#define HDIM  64
#define MTOK  (BATCH*SEQ)     // 8192
#define BH    (BATCH*HEADS)   // 48
#define ATT_SCALE 0.03608439182435161f   // 1/sqrt(768)

typedef unsigned long long u64t;

// ---- packed f32x2 helpers (proven R8) ----
__device__ __forceinline__ u64t pack2(float lo, float hi) {
    u64t r;
    asm("mov.b64 %0, {%1, %2};" : "=l"(r) : "f"(lo), "f"(hi));
    return r;
}
__device__ __forceinline__ void unpack2(u64t v, float& lo, float& hi) {
    asm("mov.b64 {%0, %1}, %2;" : "=f"(lo), "=f"(hi) : "l"(v));
}
__device__ __forceinline__ u64t fma2(u64t a, u64t b, u64t c) {
    u64t r;
    asm("fma.rn.f32x2 %0, %1, %2, %3;" : "=l"(r) : "l"(a), "l"(b), "l"(c));
    return r;
}
__device__ __forceinline__ u64t mul2(u64t a, u64t b) {
    u64t r;
    asm("mul.rn.f32x2 %0, %1, %2;" : "=l"(r) : "l"(a), "l"(b));
    return r;
}

// ---- tf32 helpers ----
__device__ __forceinline__ uint32_t f2tf32(float f) {
    uint32_t r;
    asm("cvt.rna.tf32.f32 %0, %1;" : "=r"(r) : "f"(f));
    return r;
}
__device__ __forceinline__ void mma_tf32(
    float& c0, float& c1, float& c2, float& c3,
    uint32_t a0, uint32_t a1, uint32_t a2, uint32_t a3,
    uint32_t b0, uint32_t b1)
{
    asm volatile(
        "mma.sync.aligned.m16n8k8.row.col.f32.tf32.tf32.f32 "
        "{%0,%1,%2,%3}, {%4,%5,%6,%7}, {%8,%9}, {%0,%1,%2,%3};"
        : "+f"(c0), "+f"(c1), "+f"(c2), "+f"(c3)
        : "r"(a0), "r"(a1), "r"(a2), "r"(a3), "r"(b0), "r"(b1));
}

// ---------------- device scratch ----------------
__device__ __align__(16) float g_q[(size_t)BH * SEQ * HDIM];
__device__ __align__(16) float g_k[(size_t)BH * SEQ * HDIM];
__device__ __align__(16) float g_v[(size_t)BH * SEQ * HDIM];
__device__ __align__(16) float g_att[(size_t)MTOK * EMB];   // [b*n, h*64+d]

// ================= QKV GEMM: tf32 mma, 1-D grid =================
// qkv[m][c] = sum_k x[m][k]*W_qkv[k][c] + b_qkv[c]
// scatter: which=c%3, d=(c/3)%64, h=c/192 (proven formula)
// Block tile 64(M) x 128(N) x 16(K); 8 warps as 2x4; warp tile 32x32.
#define AS_STRIDE 20
#define BS_STRIDE 132
__global__ __launch_bounds__(256) void qkv_tf32_kernel(
    const float* __restrict__ A,     // x [8192, 768]
    const float* __restrict__ B,     // W_qkv [768, 2304]
    const float* __restrict__ bias)  // b_qkv [2304]
{
    __shared__ uint32_t As[64 * AS_STRIDE];   // As[m][k] tf32 bits
    __shared__ uint32_t Bs[16 * BS_STRIDE];   // Bs[k][n] tf32 bits

    const int tid  = threadIdx.x;
    const int bm   = blockIdx.x / 18;          // 0..127  (M tiles)
    const int bn   = blockIdx.x % 18;          // 0..17   (N tiles)
    const int row0 = bm * 64;
    const int col0 = bn * 128;

    const int warp = tid >> 5;
    const int lane = tid & 31;
    const int wm   = warp >> 2;          // 0..1
    const int wn   = warp & 3;           // 0..3
    const int grp  = lane >> 2;          // 0..7
    const int tig  = lane & 3;           // 0..3

    const int a_row = tid >> 2;          // 0..63
    const int a_kc  = (tid & 3) << 2;    // 0,4,8,12
    const int br0 = tid >> 5;            // 0..7
    const int bc0 = (tid & 31) << 2;     // 0..124
    const int br1 = br0 + 8;             // 8..15

    float acc[2][4][4];
#pragma unroll
    for (int mi = 0; mi < 2; ++mi)
#pragma unroll
        for (int ni = 0; ni < 4; ++ni)
#pragma unroll
            for (int r = 0; r < 4; ++r) acc[mi][ni][r] = 0.0f;

    for (int k0 = 0; k0 < EMB; k0 += 16) {
        const float4 av  = *(const float4*)&A[(size_t)(row0 + a_row) * EMB + k0 + a_kc];
        const float4 bv0 = *(const float4*)&B[(size_t)(k0 + br0) * NQKV + col0 + bc0];
        const float4 bv1 = *(const float4*)&B[(size_t)(k0 + br1) * NQKV + col0 + bc0];

        __syncthreads();   // previous tile fully consumed
        As[a_row * AS_STRIDE + a_kc + 0] = f2tf32(av.x);
        As[a_row * AS_STRIDE + a_kc + 1] = f2tf32(av.y);
        As[a_row * AS_STRIDE + a_kc + 2] = f2tf32(av.z);
        As[a_row * AS_STRIDE + a_kc + 3] = f2tf32(av.w);
        Bs[br0 * BS_STRIDE + bc0 + 0] = f2tf32(bv0.x);
        Bs[br0 * BS_STRIDE + bc0 + 1] = f2tf32(bv0.y);
        Bs[br0 * BS_STRIDE + bc0 + 2] = f2tf32(bv0.z);
        Bs[br0 * BS_STRIDE + bc0 + 3] = f2tf32(bv0.w);
        Bs[br1 * BS_STRIDE + bc0 + 0] = f2tf32(bv1.x);
        Bs[br1 * BS_STRIDE + bc0 + 1] = f2tf32(bv1.y);
        Bs[br1 * BS_STRIDE + bc0 + 2] = f2tf32(bv1.z);
        Bs[br1 * BS_STRIDE + bc0 + 3] = f2tf32(bv1.w);
        __syncthreads();

#pragma unroll
        for (int ks = 0; ks < 2; ++ks) {
            const int kk = ks * 8;
            uint32_t afr[2][4];
#pragma unroll
            for (int mi = 0; mi < 2; ++mi) {
                const int rbase = wm * 32 + mi * 16 + grp;
                afr[mi][0] = As[(rbase)     * AS_STRIDE + kk + tig];
                afr[mi][1] = As[(rbase + 8) * AS_STRIDE + kk + tig];
                afr[mi][2] = As[(rbase)     * AS_STRIDE + kk + tig + 4];
                afr[mi][3] = As[(rbase + 8) * AS_STRIDE + kk + tig + 4];
            }
            uint32_t bfr[4][2];
#pragma unroll
            for (int ni = 0; ni < 4; ++ni) {
                const int col = wn * 32 + ni * 8 + grp;
                bfr[ni][0] = Bs[(kk + tig)     * BS_STRIDE + col];
                bfr[ni][1] = Bs[(kk + tig + 4) * BS_STRIDE + col];
            }
#pragma unroll
            for (int mi = 0; mi < 2; ++mi)
#pragma unroll
                for (int ni = 0; ni < 4; ++ni)
                    mma_tf32(acc[mi][ni][0], acc[mi][ni][1],
                             acc[mi][ni][2], acc[mi][ni][3],
                             afr[mi][0], afr[mi][1], afr[mi][2], afr[mi][3],
                             bfr[ni][0], bfr[ni][1]);
        }
    }

    // -------- epilogue: bias + proven scatter --------
#pragma unroll
    for (int mi = 0; mi < 2; ++mi) {
        const int rA = row0 + wm * 32 + mi * 16 + grp;       // rows rA, rA+8
#pragma unroll
        for (int ni = 0; ni < 4; ++ni) {
            const int cA = col0 + wn * 32 + ni * 8 + 2 * tig;  // cols cA, cA+1
#pragma unroll
            for (int r = 0; r < 4; ++r) {
                const int m = rA + ((r >= 2) ? 8 : 0);
                const int c = cA + (r & 1);
                const float s = acc[mi][ni][r] + bias[c];
                const int which = c % 3;             // 0=q,1=k,2=v (innermost)
                const int d     = (c / 3) % HDIM;
                const int h     = c / (HDIM * 3);
                const int b     = m / SEQ;
                const int n     = m % SEQ;
                float* dst = (which == 0) ? g_q : ((which == 1) ? g_k : g_v);
                dst[(((size_t)b * HEADS + h) * SEQ + n) * HDIM + d] = s;
            }
        }
    }
}

// ================= flash attention, FMA2 (PROVEN R8, verbatim) =================
__global__ __launch_bounds__(128) void attn_flash_f2_kernel()
{
    __shared__ float Ks[32 * HDIM];
    __shared__ float Vs[32 * HDIM];

    const int bh  = blockIdx.x;
    const int tid = threadIdx.x;
    const int n   = blockIdx.y * 128 + tid;

    const float4* Kb = (const float4*)(g_k + (size_t)bh * SEQ * HDIM);
    const float4* Vb = (const float4*)(g_v + (size_t)bh * SEQ * HDIM);
    const float*  qp = g_q + ((size_t)bh * SEQ + n) * HDIM;

    u64t q2[32];
#pragma unroll
    for (int d = 0; d < HDIM; d += 4) {
        const float4 t = *(const float4*)(qp + d);
        q2[d / 2]     = pack2(t.x * ATT_SCALE, t.y * ATT_SCALE);
        q2[d / 2 + 1] = pack2(t.z * ATT_SCALE, t.w * ATT_SCALE);
    }

    u64t accv[32];
#pragma unroll
    for (int t = 0; t < 32; ++t) accv[t] = 0ull;
    float mrun = -1e30f;
    float lrun = 0.0f;

    for (int kt = 0; kt < SEQ / 32; ++kt) {
        __syncthreads();
#pragma unroll
        for (int u = 0; u < 4; ++u) {
            const int i = u * 128 + tid;
            ((float4*)Ks)[i] = Kb[kt * 512 + i];
            ((float4*)Vs)[i] = Vb[kt * 512 + i];
        }
        __syncthreads();

        float s[32];
        float tmax = -1e30f;
#pragma unroll
        for (int j = 0; j < 32; ++j) {
            const ulonglong2* kr2 = (const ulonglong2*)(Ks + j * HDIM);
            u64t a01 = 0ull, a23 = 0ull;
#pragma unroll
            for (int t = 0; t < 16; ++t) {
                const ulonglong2 kv = kr2[t];
                a01 = fma2(q2[2 * t],     kv.x, a01);
                a23 = fma2(q2[2 * t + 1], kv.y, a23);
            }
            float l0, l1, l2, l3;
            unpack2(a01, l0, l1);
            unpack2(a23, l2, l3);
            s[j] = (l0 + l1) + (l2 + l3);
            tmax = fmaxf(tmax, s[j]);
        }

        const float mnew = fmaxf(mrun, tmax);
        const float corr = __expf(mrun - mnew);
        lrun *= corr;
        const u64t corr2 = pack2(corr, corr);
#pragma unroll
        for (int t = 0; t < 32; ++t) accv[t] = mul2(accv[t], corr2);
        mrun = mnew;

#pragma unroll
        for (int j = 0; j < 32; ++j) {
            const float p = __expf(s[j] - mnew);
            lrun += p;
            const u64t p2 = pack2(p, p);
            const ulonglong2* vr2 = (const ulonglong2*)(Vs + j * HDIM);
#pragma unroll
            for (int t = 0; t < 16; ++t) {
                const ulonglong2 vv = vr2[t];
                accv[2 * t]     = fma2(p2, vv.x, accv[2 * t]);
                accv[2 * t + 1] = fma2(p2, vv.y, accv[2 * t + 1]);
            }
        }
    }

    const float inv = 1.0f / lrun;
    const int b = bh / HEADS;
    const int h = bh % HEADS;
    float* op = g_att + ((size_t)(b * SEQ + n)) * EMB + h * HDIM;
#pragma unroll
    for (int d = 0; d < HDIM; d += 4) {
        float a0, a1, a2, a3;
        unpack2(accv[d / 2],     a0, a1);
        unpack2(accv[d / 2 + 1], a2, a3);
        float4 r;
        r.x = a0 * inv;
        r.y = a1 * inv;
        r.z = a2 * inv;
        r.w = a3 * inv;
        *(float4*)(op + d) = r;
    }
}

// ================= output projection, FMA2 (PROVEN R8, verbatim) =================
__global__ __launch_bounds__(256) void proj_m8c4_f2_kernel(
    const float* __restrict__ Wp,
    const float* __restrict__ bp,
    float* __restrict__ out)
{
    const int idx = blockIdx.x * 256 + threadIdx.x;
    const int mg  = idx / 192;
    const int c4  = idx % 192;
    const int m0  = mg * 8;
    const int c0  = c4 * 4;

    const float* ar = g_att + (size_t)m0 * EMB;

    u64t acc2[8][2];
#pragma unroll
    for (int i = 0; i < 8; ++i) { acc2[i][0] = 0ull; acc2[i][1] = 0ull; }

#pragma unroll 2
    for (int k4 = 0; k4 < EMB; k4 += 4) {
        const ulonglong2 wv0 = *(const ulonglong2*)&Wp[(size_t)(k4 + 0) * EMB + c0];
        const ulonglong2 wv1 = *(const ulonglong2*)&Wp[(size_t)(k4 + 1) * EMB + c0];
        const ulonglong2 wv2 = *(const ulonglong2*)&Wp[(size_t)(k4 + 2) * EMB + c0];
        const ulonglong2 wv3 = *(const ulonglong2*)&Wp[(size_t)(k4 + 3) * EMB + c0];

#pragma unroll
        for (int i = 0; i < 8; ++i) {
            const float4 av = *(const float4*)&ar[(size_t)i * EMB + k4];
            const u64t a0 = pack2(av.x, av.x);
            const u64t a1 = pack2(av.y, av.y);
            const u64t a2 = pack2(av.z, av.z);
            const u64t a3 = pack2(av.w, av.w);
            acc2[i][0] = fma2(a0, wv0.x, acc2[i][0]);
            acc2[i][1] = fma2(a0, wv0.y, acc2[i][1]);
            acc2[i][0] = fma2(a1, wv1.x, acc2[i][0]);
            acc2[i][1] = fma2(a1, wv1.y, acc2[i][1]);
            acc2[i][0] = fma2(a2, wv2.x, acc2[i][0]);
            acc2[i][1] = fma2(a2, wv2.y, acc2[i][1]);
            acc2[i][0] = fma2(a3, wv3.x, acc2[i][0]);
            acc2[i][1] = fma2(a3, wv3.y, acc2[i][1]);
        }
    }

#pragma unroll
    for (int i = 0; i < 8; ++i) {
        const int m = m0 + i;
        float a[4];
        unpack2(acc2[i][0], a[0], a[1]);
        unpack2(acc2[i][1], a[2], a[3]);
        float4 r;
        r.x = a[0] + bp[c0 + 0];
        r.y = a[1] + bp[c0 + 1];
        r.z = a[2] + bp[c0 + 2];
        r.w = a[3] + bp[c0 + 3];
        *(float4*)(out + (size_t)m * EMB + c0) = r;
    }
}

// ================= launch =================
extern "C" void kernel_launch(void* const* d_in, const int* in_sizes, int n_in,
                              void* d_out, int out_size)
{
    const float *x = nullptr, *Wqkv = nullptr, *bqkv = nullptr,
                *Wproj = nullptr, *bproj = nullptr;
    for (int i = 0; i < n_in; ++i) {
        switch (in_sizes[i]) {
            case 6291456: x     = (const float*)d_in[i]; break;
            case 1769472: Wqkv  = (const float*)d_in[i]; break;
            case 2304:    bqkv  = (const float*)d_in[i]; break;
            case 589824:  Wproj = (const float*)d_in[i]; break;
            case 768:     bproj = (const float*)d_in[i]; break;
            default: break;
        }
    }
    float* out = (float*)d_out;

    // qkv tensor-core GEMM: 128 M-tiles x 18 N-tiles = 2304 blocks (1-D grid)
    qkv_tf32_kernel<<<2304, 256>>>(x, Wqkv, bqkv);

    attn_flash_f2_kernel<<<dim3(BH, SEQ / 128), 128>>>();

    // proj: (8192/8)*(768/4) = 1024*192 threads -> 768 blocks
    proj_m8c4_f2_kernel<<<768, 256>>>(Wproj, bproj, out);

    (void)out_size;
}

// round 12
// speedup vs baseline: 4.9663x; 1.5640x over previous
#include <cuda_runtime.h>
#include <math.h>
#include <stdint.h>

#define EMB   768
#define NQKV  2304
#define BATCH 4
#define SEQ   2048
#define HEADS 12
#define HDIM  64
#define MTOK  (BATCH*SEQ)     // 8192
#define BH    (BATCH*HEADS)   // 48
#define ATT_SCALE 0.03608439182435161f   // 1/sqrt(768)

typedef unsigned long long u64t;

// ---- packed f32x2 helpers (proven R8) ----
__device__ __forceinline__ u64t pack2(float lo, float hi) {
    u64t r;
    asm("mov.b64 %0, {%1, %2};" : "=l"(r) : "f"(lo), "f"(hi));
    return r;
}
__device__ __forceinline__ void unpack2(u64t v, float& lo, float& hi) {
    asm("mov.b64 {%0, %1}, %2;" : "=f"(lo), "=f"(hi) : "l"(v));
}
__device__ __forceinline__ u64t fma2(u64t a, u64t b, u64t c) {
    u64t r;
    asm("fma.rn.f32x2 %0, %1, %2, %3;" : "=l"(r) : "l"(a), "l"(b), "l"(c));
    return r;
}

// ---- tf32 helpers ----
__device__ __forceinline__ uint32_t f2tf32(float f) {
    uint32_t r;
    asm("cvt.rna.tf32.f32 %0, %1;" : "=r"(r) : "f"(f));
    return r;
}
__device__ __forceinline__ void mma_tf32(
    float& c0, float& c1, float& c2, float& c3,
    uint32_t a0, uint32_t a1, uint32_t a2, uint32_t a3,
    uint32_t b0, uint32_t b1)
{
    asm volatile(
        "mma.sync.aligned.m16n8k8.row.col.f32.tf32.tf32.f32 "
        "{%0,%1,%2,%3}, {%4,%5,%6,%7}, {%8,%9}, {%0,%1,%2,%3};"
        : "+f"(c0), "+f"(c1), "+f"(c2), "+f"(c3)
        : "r"(a0), "r"(a1), "r"(a2), "r"(a3), "r"(b0), "r"(b1));
}

// ---------------- device scratch ----------------
__device__ __align__(16) float g_q[(size_t)BH * SEQ * HDIM];
__device__ __align__(16) float g_k[(size_t)BH * SEQ * HDIM];
__device__ __align__(16) float g_v[(size_t)BH * SEQ * HDIM];
__device__ __align__(16) float g_att[(size_t)MTOK * EMB];   // [b*n, h*64+d]

// ================= QKV GEMM: tf32 mma, 1-D grid (PROVEN R10, verbatim) =================
#define AS_STRIDE 20
#define BS_STRIDE 132
__global__ __launch_bounds__(256) void qkv_tf32_kernel(
    const float* __restrict__ A,     // x [8192, 768]
    const float* __restrict__ B,     // W_qkv [768, 2304]
    const float* __restrict__ bias)  // b_qkv [2304]
{
    __shared__ uint32_t As[64 * AS_STRIDE];
    __shared__ uint32_t Bs[16 * BS_STRIDE];

    const int tid  = threadIdx.x;
    const int bm   = blockIdx.x / 18;
    const int bn   = blockIdx.x % 18;
    const int row0 = bm * 64;
    const int col0 = bn * 128;

    const int warp = tid >> 5;
    const int lane = tid & 31;
    const int wm   = warp >> 2;
    const int wn   = warp & 3;
    const int grp  = lane >> 2;
    const int tig  = lane & 3;

    const int a_row = tid >> 2;
    const int a_kc  = (tid & 3) << 2;
    const int br0 = tid >> 5;
    const int bc0 = (tid & 31) << 2;
    const int br1 = br0 + 8;

    float acc[2][4][4];
#pragma unroll
    for (int mi = 0; mi < 2; ++mi)
#pragma unroll
        for (int ni = 0; ni < 4; ++ni)
#pragma unroll
            for (int r = 0; r < 4; ++r) acc[mi][ni][r] = 0.0f;

    for (int k0 = 0; k0 < EMB; k0 += 16) {
        const float4 av  = *(const float4*)&A[(size_t)(row0 + a_row) * EMB + k0 + a_kc];
        const float4 bv0 = *(const float4*)&B[(size_t)(k0 + br0) * NQKV + col0 + bc0];
        const float4 bv1 = *(const float4*)&B[(size_t)(k0 + br1) * NQKV + col0 + bc0];

        __syncthreads();
        As[a_row * AS_STRIDE + a_kc + 0] = f2tf32(av.x);
        As[a_row * AS_STRIDE + a_kc + 1] = f2tf32(av.y);
        As[a_row * AS_STRIDE + a_kc + 2] = f2tf32(av.z);
        As[a_row * AS_STRIDE + a_kc + 3] = f2tf32(av.w);
        Bs[br0 * BS_STRIDE + bc0 + 0] = f2tf32(bv0.x);
        Bs[br0 * BS_STRIDE + bc0 + 1] = f2tf32(bv0.y);
        Bs[br0 * BS_STRIDE + bc0 + 2] = f2tf32(bv0.z);
        Bs[br0 * BS_STRIDE + bc0 + 3] = f2tf32(bv0.w);
        Bs[br1 * BS_STRIDE + bc0 + 0] = f2tf32(bv1.x);
        Bs[br1 * BS_STRIDE + bc0 + 1] = f2tf32(bv1.y);
        Bs[br1 * BS_STRIDE + bc0 + 2] = f2tf32(bv1.z);
        Bs[br1 * BS_STRIDE + bc0 + 3] = f2tf32(bv1.w);
        __syncthreads();

#pragma unroll
        for (int ks = 0; ks < 2; ++ks) {
            const int kk = ks * 8;
            uint32_t afr[2][4];
#pragma unroll
            for (int mi = 0; mi < 2; ++mi) {
                const int rbase = wm * 32 + mi * 16 + grp;
                afr[mi][0] = As[(rbase)     * AS_STRIDE + kk + tig];
                afr[mi][1] = As[(rbase + 8) * AS_STRIDE + kk + tig];
                afr[mi][2] = As[(rbase)     * AS_STRIDE + kk + tig + 4];
                afr[mi][3] = As[(rbase + 8) * AS_STRIDE + kk + tig + 4];
            }
            uint32_t bfr[4][2];
#pragma unroll
            for (int ni = 0; ni < 4; ++ni) {
                const int col = wn * 32 + ni * 8 + grp;
                bfr[ni][0] = Bs[(kk + tig)     * BS_STRIDE + col];
                bfr[ni][1] = Bs[(kk + tig + 4) * BS_STRIDE + col];
            }
#pragma unroll
            for (int mi = 0; mi < 2; ++mi)
#pragma unroll
                for (int ni = 0; ni < 4; ++ni)
                    mma_tf32(acc[mi][ni][0], acc[mi][ni][1],
                             acc[mi][ni][2], acc[mi][ni][3],
                             afr[mi][0], afr[mi][1], afr[mi][2], afr[mi][3],
                             bfr[ni][0], bfr[ni][1]);
        }
    }

#pragma unroll
    for (int mi = 0; mi < 2; ++mi) {
        const int rA = row0 + wm * 32 + mi * 16 + grp;
#pragma unroll
        for (int ni = 0; ni < 4; ++ni) {
            const int cA = col0 + wn * 32 + ni * 8 + 2 * tig;
#pragma unroll
            for (int r = 0; r < 4; ++r) {
                const int m = rA + ((r >= 2) ? 8 : 0);
                const int c = cA + (r & 1);
                const float s = acc[mi][ni][r] + bias[c];
                const int which = c % 3;
                const int d     = (c / 3) % HDIM;
                const int h     = c / (HDIM * 3);
                const int b     = m / SEQ;
                const int n     = m % SEQ;
                float* dst = (which == 0) ? g_q : ((which == 1) ? g_k : g_v);
                dst[(((size_t)b * HEADS + h) * SEQ + n) * HDIM + d] = s;
            }
        }
    }
}

// ================= flash attention: tf32 mma, 1-D grid =================
// Block: 128 queries, 256 thr (8 warps x 16 q-rows). K-tiles of 32 keys.
#define KS_ST 33
#define VS_ST 68
#define PS_ST 36
__global__ __launch_bounds__(256) void attn_tf32_kernel()
{
    __shared__ uint32_t Ks[64 * KS_ST];    // [d][key]
    __shared__ uint32_t Vs[32 * VS_ST];    // [key][d]
    __shared__ uint32_t Ps[128 * PS_ST];   // [q][key]

    const int bx   = blockIdx.x;
    const int bh   = bx >> 4;
    const int qt   = bx & 15;
    const int tid  = threadIdx.x;
    const int warp = tid >> 5;
    const int lane = tid & 31;
    const int grp  = lane >> 2;
    const int tig  = lane & 3;
    const int q0   = qt * 128 + warp * 16;

    const float* Qb = g_q + (size_t)bh * SEQ * HDIM;
    const float* Kb = g_k + (size_t)bh * SEQ * HDIM;
    const float* Vb = g_v + (size_t)bh * SEQ * HDIM;

    uint32_t qf[8][4];
#pragma unroll
    for (int k8 = 0; k8 < 8; ++k8) {
        const int d0 = k8 * 8;
        qf[k8][0] = f2tf32(Qb[(size_t)(q0 + grp)     * HDIM + d0 + tig]     * ATT_SCALE);
        qf[k8][1] = f2tf32(Qb[(size_t)(q0 + grp + 8) * HDIM + d0 + tig]     * ATT_SCALE);
        qf[k8][2] = f2tf32(Qb[(size_t)(q0 + grp)     * HDIM + d0 + tig + 4] * ATT_SCALE);
        qf[k8][3] = f2tf32(Qb[(size_t)(q0 + grp + 8) * HDIM + d0 + tig + 4] * ATT_SCALE);
    }

    float o[8][4];
#pragma unroll
    for (int ni = 0; ni < 8; ++ni)
#pragma unroll
        for (int r = 0; r < 4; ++r) o[ni][r] = 0.0f;
    float m0r = -1e30f, m1r = -1e30f, l0r = 0.0f, l1r = 0.0f;

    for (int kt = 0; kt < SEQ / 32; ++kt) {
        __syncthreads();
#pragma unroll
        for (int i = 0; i < 2; ++i) {
            const int idx = tid + i * 256;
            const int key = idx >> 4;
            const int d   = (idx & 15) << 2;
            const float4 kv = *(const float4*)&Kb[(size_t)(kt * 32 + key) * HDIM + d];
            Ks[(d + 0) * KS_ST + key] = f2tf32(kv.x);
            Ks[(d + 1) * KS_ST + key] = f2tf32(kv.y);
            Ks[(d + 2) * KS_ST + key] = f2tf32(kv.z);
            Ks[(d + 3) * KS_ST + key] = f2tf32(kv.w);
            const float4 vv = *(const float4*)&Vb[(size_t)(kt * 32 + key) * HDIM + d];
            uint4 vt;
            vt.x = f2tf32(vv.x);
            vt.y = f2tf32(vv.y);
            vt.z = f2tf32(vv.z);
            vt.w = f2tf32(vv.w);
            *(uint4*)&Vs[key * VS_ST + d] = vt;
        }
        __syncthreads();

        float sf[4][4];
#pragma unroll
        for (int ni = 0; ni < 4; ++ni)
#pragma unroll
            for (int r = 0; r < 4; ++r) sf[ni][r] = 0.0f;
#pragma unroll
        for (int k8 = 0; k8 < 8; ++k8) {
            const int kk = k8 * 8;
#pragma unroll
            for (int ni = 0; ni < 4; ++ni) {
                const int col = ni * 8 + grp;
                const uint32_t b0 = Ks[(kk + tig)     * KS_ST + col];
                const uint32_t b1 = Ks[(kk + tig + 4) * KS_ST + col];
                mma_tf32(sf[ni][0], sf[ni][1], sf[ni][2], sf[ni][3],
                         qf[k8][0], qf[k8][1], qf[k8][2], qf[k8][3], b0, b1);
            }
        }

        float mx0 = -1e30f, mx1 = -1e30f;
#pragma unroll
        for (int ni = 0; ni < 4; ++ni) {
            mx0 = fmaxf(mx0, fmaxf(sf[ni][0], sf[ni][1]));
            mx1 = fmaxf(mx1, fmaxf(sf[ni][2], sf[ni][3]));
        }
        mx0 = fmaxf(mx0, __shfl_xor_sync(0xffffffffu, mx0, 1));
        mx0 = fmaxf(mx0, __shfl_xor_sync(0xffffffffu, mx0, 2));
        mx1 = fmaxf(mx1, __shfl_xor_sync(0xffffffffu, mx1, 1));
        mx1 = fmaxf(mx1, __shfl_xor_sync(0xffffffffu, mx1, 2));

        const float m0n = fmaxf(m0r, mx0);
        const float m1n = fmaxf(m1r, mx1);
        const float c0 = __expf(m0r - m0n);
        const float c1 = __expf(m1r - m1n);
        l0r *= c0;
        l1r *= c1;
#pragma unroll
        for (int ni = 0; ni < 8; ++ni) {
            o[ni][0] *= c0;
            o[ni][1] *= c0;
            o[ni][2] *= c1;
            o[ni][3] *= c1;
        }
        m0r = m0n;
        m1r = m1n;

        float ps0 = 0.0f, ps1 = 0.0f;
        const int prow0 = (warp * 16 + grp) * PS_ST;
        const int prow1 = (warp * 16 + grp + 8) * PS_ST;
#pragma unroll
        for (int ni = 0; ni < 4; ++ni) {
            const int col = ni * 8 + 2 * tig;
            const float p00 = __expf(sf[ni][0] - m0n);
            const float p01 = __expf(sf[ni][1] - m0n);
            const float p10 = __expf(sf[ni][2] - m1n);
            const float p11 = __expf(sf[ni][3] - m1n);
            ps0 += p00 + p01;
            ps1 += p10 + p11;
            Ps[prow0 + col]     = f2tf32(p00);
            Ps[prow0 + col + 1] = f2tf32(p01);
            Ps[prow1 + col]     = f2tf32(p10);
            Ps[prow1 + col + 1] = f2tf32(p11);
        }
        ps0 += __shfl_xor_sync(0xffffffffu, ps0, 1);
        ps0 += __shfl_xor_sync(0xffffffffu, ps0, 2);
        ps1 += __shfl_xor_sync(0xffffffffu, ps1, 1);
        ps1 += __shfl_xor_sync(0xffffffffu, ps1, 2);
        l0r += ps0;
        l1r += ps1;

        __syncwarp();

#pragma unroll
        for (int k4 = 0; k4 < 4; ++k4) {
            const int kk = k4 * 8;
            const uint32_t a0 = Ps[prow0 + kk + tig];
            const uint32_t a1 = Ps[prow1 + kk + tig];
            const uint32_t a2 = Ps[prow0 + kk + tig + 4];
            const uint32_t a3 = Ps[prow1 + kk + tig + 4];
#pragma unroll
            for (int ni = 0; ni < 8; ++ni) {
                const int col = ni * 8 + grp;
                const uint32_t b0 = Vs[(kk + tig)     * VS_ST + col];
                const uint32_t b1 = Vs[(kk + tig + 4) * VS_ST + col];
                mma_tf32(o[ni][0], o[ni][1], o[ni][2], o[ni][3],
                         a0, a1, a2, a3, b0, b1);
            }
        }
    }

    const float inv0 = 1.0f / l0r;
    const float inv1 = 1.0f / l1r;
    const int b = bh / HEADS;
    const int h = bh % HEADS;
    const size_t r0 = ((size_t)b * SEQ + (q0 + grp))     * EMB + h * HDIM;
    const size_t r1 = ((size_t)b * SEQ + (q0 + grp + 8)) * EMB + h * HDIM;
#pragma unroll
    for (int ni = 0; ni < 8; ++ni) {
        const int col = ni * 8 + 2 * tig;
        float2 w0, w1;
        w0.x = o[ni][0] * inv0;
        w0.y = o[ni][1] * inv0;
        w1.x = o[ni][2] * inv1;
        w1.y = o[ni][3] * inv1;
        *(float2*)(g_att + r0 + col) = w0;
        *(float2*)(g_att + r1 + col) = w1;
    }
}

// ================= output projection, FMA2, smem-free (PROVEN R8, verbatim) =================
__global__ __launch_bounds__(256) void proj_m8c4_f2_kernel(
    const float* __restrict__ Wp,
    const float* __restrict__ bp,
    float* __restrict__ out)
{
    const int idx = blockIdx.x * 256 + threadIdx.x;
    const int mg  = idx / 192;
    const int c4  = idx % 192;
    const int m0  = mg * 8;
    const int c0  = c4 * 4;

    const float* ar = g_att + (size_t)m0 * EMB;

    u64t acc2[8][2];
#pragma unroll
    for (int i = 0; i < 8; ++i) { acc2[i][0] = 0ull; acc2[i][1] = 0ull; }

#pragma unroll 2
    for (int k4 = 0; k4 < EMB; k4 += 4) {
        const ulonglong2 wv0 = *(const ulonglong2*)&Wp[(size_t)(k4 + 0) * EMB + c0];
        const ulonglong2 wv1 = *(const ulonglong2*)&Wp[(size_t)(k4 + 1) * EMB + c0];
        const ulonglong2 wv2 = *(const ulonglong2*)&Wp[(size_t)(k4 + 2) * EMB + c0];
        const ulonglong2 wv3 = *(const ulonglong2*)&Wp[(size_t)(k4 + 3) * EMB + c0];

#pragma unroll
        for (int i = 0; i < 8; ++i) {
            const float4 av = *(const float4*)&ar[(size_t)i * EMB + k4];
            const u64t a0 = pack2(av.x, av.x);
            const u64t a1 = pack2(av.y, av.y);
            const u64t a2 = pack2(av.z, av.z);
            const u64t a3 = pack2(av.w, av.w);
            acc2[i][0] = fma2(a0, wv0.x, acc2[i][0]);
            acc2[i][1] = fma2(a0, wv0.y, acc2[i][1]);
            acc2[i][0] = fma2(a1, wv1.x, acc2[i][0]);
            acc2[i][1] = fma2(a1, wv1.y, acc2[i][1]);
            acc2[i][0] = fma2(a2, wv2.x, acc2[i][0]);
            acc2[i][1] = fma2(a2, wv2.y, acc2[i][1]);
            acc2[i][0] = fma2(a3, wv3.x, acc2[i][0]);
            acc2[i][1] = fma2(a3, wv3.y, acc2[i][1]);
        }
    }

#pragma unroll
    for (int i = 0; i < 8; ++i) {
        const int m = m0 + i;
        float a[4];
        unpack2(acc2[i][0], a[0], a[1]);
        unpack2(acc2[i][1], a[2], a[3]);
        float4 r;
        r.x = a[0] + bp[c0 + 0];
        r.y = a[1] + bp[c0 + 1];
        r.z = a[2] + bp[c0 + 2];
        r.w = a[3] + bp[c0 + 3];
        *(float4*)(out + (size_t)m * EMB + c0) = r;
    }
}

// ================= launch =================
extern "C" void kernel_launch(void* const* d_in, const int* in_sizes, int n_in,
                              void* d_out, int out_size)
{
    const float *x = nullptr, *Wqkv = nullptr, *bqkv = nullptr,
                *Wproj = nullptr, *bproj = nullptr;
    for (int i = 0; i < n_in; ++i) {
        switch (in_sizes[i]) {
            case 6291456: x     = (const float*)d_in[i]; break;
            case 1769472: Wqkv  = (const float*)d_in[i]; break;
            case 2304:    bqkv  = (const float*)d_in[i]; break;
            case 589824:  Wproj = (const float*)d_in[i]; break;
            case 768:     bproj = (const float*)d_in[i]; break;
            default: break;
        }
    }
    float* out = (float*)d_out;

    // qkv: 128 M-tiles x 18 N-tiles = 2304 blocks (1-D grid) -- the ONE smem GEMM
    qkv_tf32_kernel<<<2304, 256>>>(x, Wqkv, bqkv);

    // attention: 48 bh x 16 q-tiles = 768 blocks (1-D grid)
    attn_tf32_kernel<<<768, 256>>>();

    // proj: smem-free FMA2 (proven)
    proj_m8c4_f2_kernel<<<768, 256>>>(Wproj, bproj, out);

    (void)out_size;
}

// round 13
// speedup vs baseline: 5.5542x; 1.1184x over previous
#include <cuda_runtime.h>
#include <math.h>
#include <stdint.h>

#define EMB   768
#define NQKV  2304
#define BATCH 4
#define SEQ   2048
#define HEADS 12
#define HDIM  64
#define MTOK  (BATCH*SEQ)     // 8192
#define BH    (BATCH*HEADS)   // 48
#define ATT_SCALE 0.03608439182435161f   // 1/sqrt(768)

typedef unsigned long long u64t;

// ---- packed f32x2 helpers (proven R8) ----
__device__ __forceinline__ u64t pack2(float lo, float hi) {
    u64t r;
    asm("mov.b64 %0, {%1, %2};" : "=l"(r) : "f"(lo), "f"(hi));
    return r;
}
__device__ __forceinline__ void unpack2(u64t v, float& lo, float& hi) {
    asm("mov.b64 {%0, %1}, %2;" : "=f"(lo), "=f"(hi) : "l"(v));
}
__device__ __forceinline__ u64t fma2(u64t a, u64t b, u64t c) {
    u64t r;
    asm("fma.rn.f32x2 %0, %1, %2, %3;" : "=l"(r) : "l"(a), "l"(b), "l"(c));
    return r;
}

// ---- tf32 helpers ----
__device__ __forceinline__ uint32_t f2tf32(float f) {
    uint32_t r;
    asm("cvt.rna.tf32.f32 %0, %1;" : "=r"(r) : "f"(f));
    return r;
}
__device__ __forceinline__ void mma_tf32(
    float& c0, float& c1, float& c2, float& c3,
    uint32_t a0, uint32_t a1, uint32_t a2, uint32_t a3,
    uint32_t b0, uint32_t b1)
{
    asm volatile(
        "mma.sync.aligned.m16n8k8.row.col.f32.tf32.tf32.f32 "
        "{%0,%1,%2,%3}, {%4,%5,%6,%7}, {%8,%9}, {%0,%1,%2,%3};"
        : "+f"(c0), "+f"(c1), "+f"(c2), "+f"(c3)
        : "r"(a0), "r"(a1), "r"(a2), "r"(a3), "r"(b0), "r"(b1));
}

// ---------------- device scratch ----------------
__device__ __align__(16) float g_q[(size_t)BH * SEQ * HDIM];
__device__ __align__(16) float g_k[(size_t)BH * SEQ * HDIM];
__device__ __align__(16) float g_v[(size_t)BH * SEQ * HDIM];
__device__ __align__(16) float g_att[(size_t)MTOK * EMB];   // [b*n, h*64+d]

// ================= QKV GEMM: tf32 mma, 1-D grid (PROVEN R10/R12, verbatim) =================
#define AS_STRIDE 20
#define BS_STRIDE 132
__global__ __launch_bounds__(256) void qkv_tf32_kernel(
    const float* __restrict__ A,     // x [8192, 768]
    const float* __restrict__ B,     // W_qkv [768, 2304]
    const float* __restrict__ bias)  // b_qkv [2304]
{
    __shared__ uint32_t As[64 * AS_STRIDE];
    __shared__ uint32_t Bs[16 * BS_STRIDE];

    const int tid  = threadIdx.x;
    const int bm   = blockIdx.x / 18;
    const int bn   = blockIdx.x % 18;
    const int row0 = bm * 64;
    const int col0 = bn * 128;

    const int warp = tid >> 5;
    const int lane = tid & 31;
    const int wm   = warp >> 2;
    const int wn   = warp & 3;
    const int grp  = lane >> 2;
    const int tig  = lane & 3;

    const int a_row = tid >> 2;
    const int a_kc  = (tid & 3) << 2;
    const int br0 = tid >> 5;
    const int bc0 = (tid & 31) << 2;
    const int br1 = br0 + 8;

    float acc[2][4][4];
#pragma unroll
    for (int mi = 0; mi < 2; ++mi)
#pragma unroll
        for (int ni = 0; ni < 4; ++ni)
#pragma unroll
            for (int r = 0; r < 4; ++r) acc[mi][ni][r] = 0.0f;

    for (int k0 = 0; k0 < EMB; k0 += 16) {
        const float4 av  = *(const float4*)&A[(size_t)(row0 + a_row) * EMB + k0 + a_kc];
        const float4 bv0 = *(const float4*)&B[(size_t)(k0 + br0) * NQKV + col0 + bc0];
        const float4 bv1 = *(const float4*)&B[(size_t)(k0 + br1) * NQKV + col0 + bc0];

        __syncthreads();
        As[a_row * AS_STRIDE + a_kc + 0] = f2tf32(av.x);
        As[a_row * AS_STRIDE + a_kc + 1] = f2tf32(av.y);
        As[a_row * AS_STRIDE + a_kc + 2] = f2tf32(av.z);
        As[a_row * AS_STRIDE + a_kc + 3] = f2tf32(av.w);
        Bs[br0 * BS_STRIDE + bc0 + 0] = f2tf32(bv0.x);
        Bs[br0 * BS_STRIDE + bc0 + 1] = f2tf32(bv0.y);
        Bs[br0 * BS_STRIDE + bc0 + 2] = f2tf32(bv0.z);
        Bs[br0 * BS_STRIDE + bc0 + 3] = f2tf32(bv0.w);
        Bs[br1 * BS_STRIDE + bc0 + 0] = f2tf32(bv1.x);
        Bs[br1 * BS_STRIDE + bc0 + 1] = f2tf32(bv1.y);
        Bs[br1 * BS_STRIDE + bc0 + 2] = f2tf32(bv1.z);
        Bs[br1 * BS_STRIDE + bc0 + 3] = f2tf32(bv1.w);
        __syncthreads();

#pragma unroll
        for (int ks = 0; ks < 2; ++ks) {
            const int kk = ks * 8;
            uint32_t afr[2][4];
#pragma unroll
            for (int mi = 0; mi < 2; ++mi) {
                const int rbase = wm * 32 + mi * 16 + grp;
                afr[mi][0] = As[(rbase)     * AS_STRIDE + kk + tig];
                afr[mi][1] = As[(rbase + 8) * AS_STRIDE + kk + tig];
                afr[mi][2] = As[(rbase)     * AS_STRIDE + kk + tig + 4];
                afr[mi][3] = As[(rbase + 8) * AS_STRIDE + kk + tig + 4];
            }
            uint32_t bfr[4][2];
#pragma unroll
            for (int ni = 0; ni < 4; ++ni) {
                const int col = wn * 32 + ni * 8 + grp;
                bfr[ni][0] = Bs[(kk + tig)     * BS_STRIDE + col];
                bfr[ni][1] = Bs[(kk + tig + 4) * BS_STRIDE + col];
            }
#pragma unroll
            for (int mi = 0; mi < 2; ++mi)
#pragma unroll
                for (int ni = 0; ni < 4; ++ni)
                    mma_tf32(acc[mi][ni][0], acc[mi][ni][1],
                             acc[mi][ni][2], acc[mi][ni][3],
                             afr[mi][0], afr[mi][1], afr[mi][2], afr[mi][3],
                             bfr[ni][0], bfr[ni][1]);
        }
    }

#pragma unroll
    for (int mi = 0; mi < 2; ++mi) {
        const int rA = row0 + wm * 32 + mi * 16 + grp;
#pragma unroll
        for (int ni = 0; ni < 4; ++ni) {
            const int cA = col0 + wn * 32 + ni * 8 + 2 * tig;
#pragma unroll
            for (int r = 0; r < 4; ++r) {
                const int m = rA + ((r >= 2) ? 8 : 0);
                const int c = cA + (r & 1);
                const float s = acc[mi][ni][r] + bias[c];
                const int which = c % 3;
                const int d     = (c / 3) % HDIM;
                const int h     = c / (HDIM * 3);
                const int b     = m / SEQ;
                const int n     = m % SEQ;
                float* dst = (which == 0) ? g_q : ((which == 1) ? g_k : g_v);
                dst[(((size_t)b * HEADS + h) * SEQ + n) * HDIM + d] = s;
            }
        }
    }
}

// ================= flash attention: tf32 mma, prefetch + conflict-free Ks =================
// Same algorithm/index algebra as PROVEN R12 kernel; changes:
//   (a) KS_ST 33 -> 36 (conflict-free B-fragment LDS)
//   (b) global K/V loads for tile kt+1 prefetched into registers during tile kt compute
#define KS_ST 36
#define VS_ST 68
#define PS_ST 36
__global__ __launch_bounds__(256) void attn_tf32_kernel()
{
    __shared__ uint32_t Ks[64 * KS_ST];    // [d][key]
    __shared__ uint32_t Vs[32 * VS_ST];    // [key][d]
    __shared__ uint32_t Ps[128 * PS_ST];   // [q][key]

    const int bx   = blockIdx.x;
    const int bh   = bx >> 4;
    const int qt   = bx & 15;
    const int tid  = threadIdx.x;
    const int warp = tid >> 5;
    const int lane = tid & 31;
    const int grp  = lane >> 2;
    const int tig  = lane & 3;
    const int q0   = qt * 128 + warp * 16;

    const float* Qb = g_q + (size_t)bh * SEQ * HDIM;
    const float* Kb = g_k + (size_t)bh * SEQ * HDIM;
    const float* Vb = g_v + (size_t)bh * SEQ * HDIM;

    // per-thread staging coordinates (identical to R12)
    const int st_key0 = tid >> 4;              // i=0 : keys 0..15
    const int st_key1 = (tid + 256) >> 4;      // i=1 : keys 16..31
    const int st_d    = (tid & 15) << 2;       // 0..60

    uint32_t qf[8][4];
#pragma unroll
    for (int k8 = 0; k8 < 8; ++k8) {
        const int d0 = k8 * 8;
        qf[k8][0] = f2tf32(Qb[(size_t)(q0 + grp)     * HDIM + d0 + tig]     * ATT_SCALE);
        qf[k8][1] = f2tf32(Qb[(size_t)(q0 + grp + 8) * HDIM + d0 + tig]     * ATT_SCALE);
        qf[k8][2] = f2tf32(Qb[(size_t)(q0 + grp)     * HDIM + d0 + tig + 4] * ATT_SCALE);
        qf[k8][3] = f2tf32(Qb[(size_t)(q0 + grp + 8) * HDIM + d0 + tig + 4] * ATT_SCALE);
    }

    float o[8][4];
#pragma unroll
    for (int ni = 0; ni < 8; ++ni)
#pragma unroll
        for (int r = 0; r < 4; ++r) o[ni][r] = 0.0f;
    float m0r = -1e30f, m1r = -1e30f, l0r = 0.0f, l1r = 0.0f;

    // ---- prefetch tile 0 ----
    float4 kpre0 = *(const float4*)&Kb[(size_t)st_key0 * HDIM + st_d];
    float4 kpre1 = *(const float4*)&Kb[(size_t)st_key1 * HDIM + st_d];
    float4 vpre0 = *(const float4*)&Vb[(size_t)st_key0 * HDIM + st_d];
    float4 vpre1 = *(const float4*)&Vb[(size_t)st_key1 * HDIM + st_d];

    for (int kt = 0; kt < SEQ / 32; ++kt) {
        __syncthreads();   // previous tile fully consumed
        // ---- store prefetched K (transposed) / V tiles, tf32-converted ----
        Ks[(st_d + 0) * KS_ST + st_key0] = f2tf32(kpre0.x);
        Ks[(st_d + 1) * KS_ST + st_key0] = f2tf32(kpre0.y);
        Ks[(st_d + 2) * KS_ST + st_key0] = f2tf32(kpre0.z);
        Ks[(st_d + 3) * KS_ST + st_key0] = f2tf32(kpre0.w);
        Ks[(st_d + 0) * KS_ST + st_key1] = f2tf32(kpre1.x);
        Ks[(st_d + 1) * KS_ST + st_key1] = f2tf32(kpre1.y);
        Ks[(st_d + 2) * KS_ST + st_key1] = f2tf32(kpre1.z);
        Ks[(st_d + 3) * KS_ST + st_key1] = f2tf32(kpre1.w);
        {
            uint4 vt0, vt1;
            vt0.x = f2tf32(vpre0.x);
            vt0.y = f2tf32(vpre0.y);
            vt0.z = f2tf32(vpre0.z);
            vt0.w = f2tf32(vpre0.w);
            vt1.x = f2tf32(vpre1.x);
            vt1.y = f2tf32(vpre1.y);
            vt1.z = f2tf32(vpre1.z);
            vt1.w = f2tf32(vpre1.w);
            *(uint4*)&Vs[st_key0 * VS_ST + st_d] = vt0;
            *(uint4*)&Vs[st_key1 * VS_ST + st_d] = vt1;
        }
        __syncthreads();

        // ---- prefetch next tile (overlaps with compute below) ----
        if (kt + 1 < SEQ / 32) {
            const size_t base = (size_t)(kt + 1) * 32 * HDIM;
            kpre0 = *(const float4*)&Kb[base + (size_t)st_key0 * HDIM + st_d];
            kpre1 = *(const float4*)&Kb[base + (size_t)st_key1 * HDIM + st_d];
            vpre0 = *(const float4*)&Vb[base + (size_t)st_key0 * HDIM + st_d];
            vpre1 = *(const float4*)&Vb[base + (size_t)st_key1 * HDIM + st_d];
        }

        // ---- S = Q*K^T ----
        float sf[4][4];
#pragma unroll
        for (int ni = 0; ni < 4; ++ni)
#pragma unroll
            for (int r = 0; r < 4; ++r) sf[ni][r] = 0.0f;
#pragma unroll
        for (int k8 = 0; k8 < 8; ++k8) {
            const int kk = k8 * 8;
#pragma unroll
            for (int ni = 0; ni < 4; ++ni) {
                const int col = ni * 8 + grp;
                const uint32_t b0 = Ks[(kk + tig)     * KS_ST + col];
                const uint32_t b1 = Ks[(kk + tig + 4) * KS_ST + col];
                mma_tf32(sf[ni][0], sf[ni][1], sf[ni][2], sf[ni][3],
                         qf[k8][0], qf[k8][1], qf[k8][2], qf[k8][3], b0, b1);
            }
        }

        // ---- online softmax ----
        float mx0 = -1e30f, mx1 = -1e30f;
#pragma unroll
        for (int ni = 0; ni < 4; ++ni) {
            mx0 = fmaxf(mx0, fmaxf(sf[ni][0], sf[ni][1]));
            mx1 = fmaxf(mx1, fmaxf(sf[ni][2], sf[ni][3]));
        }
        mx0 = fmaxf(mx0, __shfl_xor_sync(0xffffffffu, mx0, 1));
        mx0 = fmaxf(mx0, __shfl_xor_sync(0xffffffffu, mx0, 2));
        mx1 = fmaxf(mx1, __shfl_xor_sync(0xffffffffu, mx1, 1));
        mx1 = fmaxf(mx1, __shfl_xor_sync(0xffffffffu, mx1, 2));

        const float m0n = fmaxf(m0r, mx0);
        const float m1n = fmaxf(m1r, mx1);
        const float c0 = __expf(m0r - m0n);
        const float c1 = __expf(m1r - m1n);
        l0r *= c0;
        l1r *= c1;
#pragma unroll
        for (int ni = 0; ni < 8; ++ni) {
            o[ni][0] *= c0;
            o[ni][1] *= c0;
            o[ni][2] *= c1;
            o[ni][3] *= c1;
        }
        m0r = m0n;
        m1r = m1n;

        float ps0 = 0.0f, ps1 = 0.0f;
        const int prow0 = (warp * 16 + grp) * PS_ST;
        const int prow1 = (warp * 16 + grp + 8) * PS_ST;
#pragma unroll
        for (int ni = 0; ni < 4; ++ni) {
            const int col = ni * 8 + 2 * tig;
            const float p00 = __expf(sf[ni][0] - m0n);
            const float p01 = __expf(sf[ni][1] - m0n);
            const float p10 = __expf(sf[ni][2] - m1n);
            const float p11 = __expf(sf[ni][3] - m1n);
            ps0 += p00 + p01;
            ps1 += p10 + p11;
            Ps[prow0 + col]     = f2tf32(p00);
            Ps[prow0 + col + 1] = f2tf32(p01);
            Ps[prow1 + col]     = f2tf32(p10);
            Ps[prow1 + col + 1] = f2tf32(p11);
        }
        ps0 += __shfl_xor_sync(0xffffffffu, ps0, 1);
        ps0 += __shfl_xor_sync(0xffffffffu, ps0, 2);
        ps1 += __shfl_xor_sync(0xffffffffu, ps1, 1);
        ps1 += __shfl_xor_sync(0xffffffffu, ps1, 2);
        l0r += ps0;
        l1r += ps1;

        __syncwarp();   // warp-private P region visible

        // ---- O += P*V ----
#pragma unroll
        for (int k4 = 0; k4 < 4; ++k4) {
            const int kk = k4 * 8;
            const uint32_t a0 = Ps[prow0 + kk + tig];
            const uint32_t a1 = Ps[prow1 + kk + tig];
            const uint32_t a2 = Ps[prow0 + kk + tig + 4];
            const uint32_t a3 = Ps[prow1 + kk + tig + 4];
#pragma unroll
            for (int ni = 0; ni < 8; ++ni) {
                const int col = ni * 8 + grp;
                const uint32_t b0 = Vs[(kk + tig)     * VS_ST + col];
                const uint32_t b1 = Vs[(kk + tig + 4) * VS_ST + col];
                mma_tf32(o[ni][0], o[ni][1], o[ni][2], o[ni][3],
                         a0, a1, a2, a3, b0, b1);
            }
        }
    }

    const float inv0 = 1.0f / l0r;
    const float inv1 = 1.0f / l1r;
    const int b = bh / HEADS;
    const int h = bh % HEADS;
    const size_t r0 = ((size_t)b * SEQ + (q0 + grp))     * EMB + h * HDIM;
    const size_t r1 = ((size_t)b * SEQ + (q0 + grp + 8)) * EMB + h * HDIM;
#pragma unroll
    for (int ni = 0; ni < 8; ++ni) {
        const int col = ni * 8 + 2 * tig;
        float2 w0, w1;
        w0.x = o[ni][0] * inv0;
        w0.y = o[ni][1] * inv0;
        w1.x = o[ni][2] * inv1;
        w1.y = o[ni][3] * inv1;
        *(float2*)(g_att + r0 + col) = w0;
        *(float2*)(g_att + r1 + col) = w1;
    }
}

// ================= output projection, FMA2, smem-free (PROVEN R8, verbatim) =================
__global__ __launch_bounds__(256) void proj_m8c4_f2_kernel(
    const float* __restrict__ Wp,
    const float* __restrict__ bp,
    float* __restrict__ out)
{
    const int idx = blockIdx.x * 256 + threadIdx.x;
    const int mg  = idx / 192;
    const int c4  = idx % 192;
    const int m0  = mg * 8;
    const int c0  = c4 * 4;

    const float* ar = g_att + (size_t)m0 * EMB;

    u64t acc2[8][2];
#pragma unroll
    for (int i = 0; i < 8; ++i) { acc2[i][0] = 0ull; acc2[i][1] = 0ull; }

#pragma unroll 2
    for (int k4 = 0; k4 < EMB; k4 += 4) {
        const ulonglong2 wv0 = *(const ulonglong2*)&Wp[(size_t)(k4 + 0) * EMB + c0];
        const ulonglong2 wv1 = *(const ulonglong2*)&Wp[(size_t)(k4 + 1) * EMB + c0];
        const ulonglong2 wv2 = *(const ulonglong2*)&Wp[(size_t)(k4 + 2) * EMB + c0];
        const ulonglong2 wv3 = *(const ulonglong2*)&Wp[(size_t)(k4 + 3) * EMB + c0];

#pragma unroll
        for (int i = 0; i < 8; ++i) {
            const float4 av = *(const float4*)&ar[(size_t)i * EMB + k4];
            const u64t a0 = pack2(av.x, av.x);
            const u64t a1 = pack2(av.y, av.y);
            const u64t a2 = pack2(av.z, av.z);
            const u64t a3 = pack2(av.w, av.w);
            acc2[i][0] = fma2(a0, wv0.x, acc2[i][0]);
            acc2[i][1] = fma2(a0, wv0.y, acc2[i][1]);
            acc2[i][0] = fma2(a1, wv1.x, acc2[i][0]);
            acc2[i][1] = fma2(a1, wv1.y, acc2[i][1]);
            acc2[i][0] = fma2(a2, wv2.x, acc2[i][0]);
            acc2[i][1] = fma2(a2, wv2.y, acc2[i][1]);
            acc2[i][0] = fma2(a3, wv3.x, acc2[i][0]);
            acc2[i][1] = fma2(a3, wv3.y, acc2[i][1]);
        }
    }

#pragma unroll
    for (int i = 0; i < 8; ++i) {
        const int m = m0 + i;
        float a[4];
        unpack2(acc2[i][0], a[0], a[1]);
        unpack2(acc2[i][1], a[2], a[3]);
        float4 r;
        r.x = a[0] + bp[c0 + 0];
        r.y = a[1] + bp[c0 + 1];
        r.z = a[2] + bp[c0 + 2];
        r.w = a[3] + bp[c0 + 3];
        *(float4*)(out + (size_t)m * EMB + c0) = r;
    }
}

// ================= launch =================
extern "C" void kernel_launch(void* const* d_in, const int* in_sizes, int n_in,
                              void* d_out, int out_size)
{
    const float *x = nullptr, *Wqkv = nullptr, *bqkv = nullptr,
                *Wproj = nullptr, *bproj = nullptr;
    for (int i = 0; i < n_in; ++i) {
        switch (in_sizes[i]) {
            case 6291456: x     = (const float*)d_in[i]; break;
            case 1769472: Wqkv  = (const float*)d_in[i]; break;
            case 2304:    bqkv  = (const float*)d_in[i]; break;
            case 589824:  Wproj = (const float*)d_in[i]; break;
            case 768:     bproj = (const float*)d_in[i]; break;
            default: break;
        }
    }
    float* out = (float*)d_out;

    // qkv: 128 M-tiles x 18 N-tiles = 2304 blocks (1-D grid)
    qkv_tf32_kernel<<<2304, 256>>>(x, Wqkv, bqkv);

    // attention: 48 bh x 16 q-tiles = 768 blocks (1-D grid)
    attn_tf32_kernel<<<768, 256>>>();

    // proj: smem-free FMA2 (proven)
    proj_m8c4_f2_kernel<<<768, 256>>>(Wproj, bproj, out);

    (void)out_size;
}

// round 14
// speedup vs baseline: 5.6630x; 1.0196x over previous
#include <cuda_runtime.h>
#include <math.h>
#include <stdint.h>

#define EMB   768
#define NQKV  2304
#define BATCH 4
#define SEQ   2048
#define HEADS 12
#define HDIM  64
#define MTOK  (BATCH*SEQ)     // 8192
#define BH    (BATCH*HEADS)   // 48
#define ATT_SCALE 0.03608439182435161f   // 1/sqrt(768)

typedef unsigned long long u64t;

// ---- packed f32x2 helpers (proven R8) ----
__device__ __forceinline__ u64t pack2(float lo, float hi) {
    u64t r;
    asm("mov.b64 %0, {%1, %2};" : "=l"(r) : "f"(lo), "f"(hi));
    return r;
}
__device__ __forceinline__ void unpack2(u64t v, float& lo, float& hi) {
    asm("mov.b64 {%0, %1}, %2;" : "=f"(lo), "=f"(hi) : "l"(v));
}
__device__ __forceinline__ u64t fma2(u64t a, u64t b, u64t c) {
    u64t r;
    asm("fma.rn.f32x2 %0, %1, %2, %3;" : "=l"(r) : "l"(a), "l"(b), "l"(c));
    return r;
}

// ---- tf32 helpers ----
__device__ __forceinline__ uint32_t f2tf32(float f) {
    uint32_t r;
    asm("cvt.rna.tf32.f32 %0, %1;" : "=r"(r) : "f"(f));
    return r;
}
__device__ __forceinline__ void mma_tf32(
    float& c0, float& c1, float& c2, float& c3,
    uint32_t a0, uint32_t a1, uint32_t a2, uint32_t a3,
    uint32_t b0, uint32_t b1)
{
    asm volatile(
        "mma.sync.aligned.m16n8k8.row.col.f32.tf32.tf32.f32 "
        "{%0,%1,%2,%3}, {%4,%5,%6,%7}, {%8,%9}, {%0,%1,%2,%3};"
        : "+f"(c0), "+f"(c1), "+f"(c2), "+f"(c3)
        : "r"(a0), "r"(a1), "r"(a2), "r"(a3), "r"(b0), "r"(b1));
}

// ---------------- device scratch ----------------
__device__ __align__(16) float g_q[(size_t)BH * SEQ * HDIM];
__device__ __align__(16) float g_k[(size_t)BH * SEQ * HDIM];
__device__ __align__(16) float g_v[(size_t)BH * SEQ * HDIM];
__device__ __align__(16) float g_att[(size_t)MTOK * EMB];   // [b*n, h*64+d]

// ================= QKV GEMM: tf32 mma, 1-D grid =================
// PROVEN R10/R12/R13 structure; only change: BS_STRIDE 132 -> 136
// (load bank = 8*tig+grp, conflict-free; stores unchanged).
#define AS_STRIDE 20
#define BS_STRIDE 136
__global__ __launch_bounds__(256) void qkv_tf32_kernel(
    const float* __restrict__ A,     // x [8192, 768]
    const float* __restrict__ B,     // W_qkv [768, 2304]
    const float* __restrict__ bias)  // b_qkv [2304]
{
    __shared__ uint32_t As[64 * AS_STRIDE];
    __shared__ uint32_t Bs[16 * BS_STRIDE];

    const int tid  = threadIdx.x;
    const int bm   = blockIdx.x / 18;
    const int bn   = blockIdx.x % 18;
    const int row0 = bm * 64;
    const int col0 = bn * 128;

    const int warp = tid >> 5;
    const int lane = tid & 31;
    const int wm   = warp >> 2;
    const int wn   = warp & 3;
    const int grp  = lane >> 2;
    const int tig  = lane & 3;

    const int a_row = tid >> 2;
    const int a_kc  = (tid & 3) << 2;
    const int br0 = tid >> 5;
    const int bc0 = (tid & 31) << 2;
    const int br1 = br0 + 8;

    float acc[2][4][4];
#pragma unroll
    for (int mi = 0; mi < 2; ++mi)
#pragma unroll
        for (int ni = 0; ni < 4; ++ni)
#pragma unroll
            for (int r = 0; r < 4; ++r) acc[mi][ni][r] = 0.0f;

    for (int k0 = 0; k0 < EMB; k0 += 16) {
        const float4 av  = *(const float4*)&A[(size_t)(row0 + a_row) * EMB + k0 + a_kc];
        const float4 bv0 = *(const float4*)&B[(size_t)(k0 + br0) * NQKV + col0 + bc0];
        const float4 bv1 = *(const float4*)&B[(size_t)(k0 + br1) * NQKV + col0 + bc0];

        __syncthreads();
        As[a_row * AS_STRIDE + a_kc + 0] = f2tf32(av.x);
        As[a_row * AS_STRIDE + a_kc + 1] = f2tf32(av.y);
        As[a_row * AS_STRIDE + a_kc + 2] = f2tf32(av.z);
        As[a_row * AS_STRIDE + a_kc + 3] = f2tf32(av.w);
        Bs[br0 * BS_STRIDE + bc0 + 0] = f2tf32(bv0.x);
        Bs[br0 * BS_STRIDE + bc0 + 1] = f2tf32(bv0.y);
        Bs[br0 * BS_STRIDE + bc0 + 2] = f2tf32(bv0.z);
        Bs[br0 * BS_STRIDE + bc0 + 3] = f2tf32(bv0.w);
        Bs[br1 * BS_STRIDE + bc0 + 0] = f2tf32(bv1.x);
        Bs[br1 * BS_STRIDE + bc0 + 1] = f2tf32(bv1.y);
        Bs[br1 * BS_STRIDE + bc0 + 2] = f2tf32(bv1.z);
        Bs[br1 * BS_STRIDE + bc0 + 3] = f2tf32(bv1.w);
        __syncthreads();

#pragma unroll
        for (int ks = 0; ks < 2; ++ks) {
            const int kk = ks * 8;
            uint32_t afr[2][4];
#pragma unroll
            for (int mi = 0; mi < 2; ++mi) {
                const int rbase = wm * 32 + mi * 16 + grp;
                afr[mi][0] = As[(rbase)     * AS_STRIDE + kk + tig];
                afr[mi][1] = As[(rbase + 8) * AS_STRIDE + kk + tig];
                afr[mi][2] = As[(rbase)     * AS_STRIDE + kk + tig + 4];
                afr[mi][3] = As[(rbase + 8) * AS_STRIDE + kk + tig + 4];
            }
            uint32_t bfr[4][2];
#pragma unroll
            for (int ni = 0; ni < 4; ++ni) {
                const int col = wn * 32 + ni * 8 + grp;
                bfr[ni][0] = Bs[(kk + tig)     * BS_STRIDE + col];
                bfr[ni][1] = Bs[(kk + tig + 4) * BS_STRIDE + col];
            }
#pragma unroll
            for (int mi = 0; mi < 2; ++mi)
#pragma unroll
                for (int ni = 0; ni < 4; ++ni)
                    mma_tf32(acc[mi][ni][0], acc[mi][ni][1],
                             acc[mi][ni][2], acc[mi][ni][3],
                             afr[mi][0], afr[mi][1], afr[mi][2], afr[mi][3],
                             bfr[ni][0], bfr[ni][1]);
        }
    }

#pragma unroll
    for (int mi = 0; mi < 2; ++mi) {
        const int rA = row0 + wm * 32 + mi * 16 + grp;
#pragma unroll
        for (int ni = 0; ni < 4; ++ni) {
            const int cA = col0 + wn * 32 + ni * 8 + 2 * tig;
#pragma unroll
            for (int r = 0; r < 4; ++r) {
                const int m = rA + ((r >= 2) ? 8 : 0);
                const int c = cA + (r & 1);
                const float s = acc[mi][ni][r] + bias[c];
                const int which = c % 3;
                const int d     = (c / 3) % HDIM;
                const int h     = c / (HDIM * 3);
                const int b     = m / SEQ;
                const int n     = m % SEQ;
                float* dst = (which == 0) ? g_q : ((which == 1) ? g_k : g_v);
                dst[(((size_t)b * HEADS + h) * SEQ + n) * HDIM + d] = s;
            }
        }
    }
}

// ================= flash attention: tf32 mma (PROVEN R13) + occupancy 2 =================
#define KS_ST 36
#define VS_ST 68
#define PS_ST 36
__global__ __launch_bounds__(256, 2) void attn_tf32_kernel()
{
    __shared__ uint32_t Ks[64 * KS_ST];    // [d][key]
    __shared__ uint32_t Vs[32 * VS_ST];    // [key][d]
    __shared__ uint32_t Ps[128 * PS_ST];   // [q][key]

    const int bx   = blockIdx.x;
    const int bh   = bx >> 4;
    const int qt   = bx & 15;
    const int tid  = threadIdx.x;
    const int warp = tid >> 5;
    const int lane = tid & 31;
    const int grp  = lane >> 2;
    const int tig  = lane & 3;
    const int q0   = qt * 128 + warp * 16;

    const float* Qb = g_q + (size_t)bh * SEQ * HDIM;
    const float* Kb = g_k + (size_t)bh * SEQ * HDIM;
    const float* Vb = g_v + (size_t)bh * SEQ * HDIM;

    const int st_key0 = tid >> 4;
    const int st_key1 = (tid + 256) >> 4;
    const int st_d    = (tid & 15) << 2;

    uint32_t qf[8][4];
#pragma unroll
    for (int k8 = 0; k8 < 8; ++k8) {
        const int d0 = k8 * 8;
        qf[k8][0] = f2tf32(Qb[(size_t)(q0 + grp)     * HDIM + d0 + tig]     * ATT_SCALE);
        qf[k8][1] = f2tf32(Qb[(size_t)(q0 + grp + 8) * HDIM + d0 + tig]     * ATT_SCALE);
        qf[k8][2] = f2tf32(Qb[(size_t)(q0 + grp)     * HDIM + d0 + tig + 4] * ATT_SCALE);
        qf[k8][3] = f2tf32(Qb[(size_t)(q0 + grp + 8) * HDIM + d0 + tig + 4] * ATT_SCALE);
    }

    float o[8][4];
#pragma unroll
    for (int ni = 0; ni < 8; ++ni)
#pragma unroll
        for (int r = 0; r < 4; ++r) o[ni][r] = 0.0f;
    float m0r = -1e30f, m1r = -1e30f, l0r = 0.0f, l1r = 0.0f;

    float4 kpre0 = *(const float4*)&Kb[(size_t)st_key0 * HDIM + st_d];
    float4 kpre1 = *(const float4*)&Kb[(size_t)st_key1 * HDIM + st_d];
    float4 vpre0 = *(const float4*)&Vb[(size_t)st_key0 * HDIM + st_d];
    float4 vpre1 = *(const float4*)&Vb[(size_t)st_key1 * HDIM + st_d];

    for (int kt = 0; kt < SEQ / 32; ++kt) {
        __syncthreads();
        Ks[(st_d + 0) * KS_ST + st_key0] = f2tf32(kpre0.x);
        Ks[(st_d + 1) * KS_ST + st_key0] = f2tf32(kpre0.y);
        Ks[(st_d + 2) * KS_ST + st_key0] = f2tf32(kpre0.z);
        Ks[(st_d + 3) * KS_ST + st_key0] = f2tf32(kpre0.w);
        Ks[(st_d + 0) * KS_ST + st_key1] = f2tf32(kpre1.x);
        Ks[(st_d + 1) * KS_ST + st_key1] = f2tf32(kpre1.y);
        Ks[(st_d + 2) * KS_ST + st_key1] = f2tf32(kpre1.z);
        Ks[(st_d + 3) * KS_ST + st_key1] = f2tf32(kpre1.w);
        {
            uint4 vt0, vt1;
            vt0.x = f2tf32(vpre0.x);
            vt0.y = f2tf32(vpre0.y);
            vt0.z = f2tf32(vpre0.z);
            vt0.w = f2tf32(vpre0.w);
            vt1.x = f2tf32(vpre1.x);
            vt1.y = f2tf32(vpre1.y);
            vt1.z = f2tf32(vpre1.z);
            vt1.w = f2tf32(vpre1.w);
            *(uint4*)&Vs[st_key0 * VS_ST + st_d] = vt0;
            *(uint4*)&Vs[st_key1 * VS_ST + st_d] = vt1;
        }
        __syncthreads();

        if (kt + 1 < SEQ / 32) {
            const size_t base = (size_t)(kt + 1) * 32 * HDIM;
            kpre0 = *(const float4*)&Kb[base + (size_t)st_key0 * HDIM + st_d];
            kpre1 = *(const float4*)&Kb[base + (size_t)st_key1 * HDIM + st_d];
            vpre0 = *(const float4*)&Vb[base + (size_t)st_key0 * HDIM + st_d];
            vpre1 = *(const float4*)&Vb[base + (size_t)st_key1 * HDIM + st_d];
        }

        float sf[4][4];
#pragma unroll
        for (int ni = 0; ni < 4; ++ni)
#pragma unroll
            for (int r = 0; r < 4; ++r) sf[ni][r] = 0.0f;
#pragma unroll
        for (int k8 = 0; k8 < 8; ++k8) {
            const int kk = k8 * 8;
#pragma unroll
            for (int ni = 0; ni < 4; ++ni) {
                const int col = ni * 8 + grp;
                const uint32_t b0 = Ks[(kk + tig)     * KS_ST + col];
                const uint32_t b1 = Ks[(kk + tig + 4) * KS_ST + col];
                mma_tf32(sf[ni][0], sf[ni][1], sf[ni][2], sf[ni][3],
                         qf[k8][0], qf[k8][1], qf[k8][2], qf[k8][3], b0, b1);
            }
        }

        float mx0 = -1e30f, mx1 = -1e30f;
#pragma unroll
        for (int ni = 0; ni < 4; ++ni) {
            mx0 = fmaxf(mx0, fmaxf(sf[ni][0], sf[ni][1]));
            mx1 = fmaxf(mx1, fmaxf(sf[ni][2], sf[ni][3]));
        }
        mx0 = fmaxf(mx0, __shfl_xor_sync(0xffffffffu, mx0, 1));
        mx0 = fmaxf(mx0, __shfl_xor_sync(0xffffffffu, mx0, 2));
        mx1 = fmaxf(mx1, __shfl_xor_sync(0xffffffffu, mx1, 1));
        mx1 = fmaxf(mx1, __shfl_xor_sync(0xffffffffu, mx1, 2));

        const float m0n = fmaxf(m0r, mx0);
        const float m1n = fmaxf(m1r, mx1);
        const float c0 = __expf(m0r - m0n);
        const float c1 = __expf(m1r - m1n);
        l0r *= c0;
        l1r *= c1;
#pragma unroll
        for (int ni = 0; ni < 8; ++ni) {
            o[ni][0] *= c0;
            o[ni][1] *= c0;
            o[ni][2] *= c1;
            o[ni][3] *= c1;
        }
        m0r = m0n;
        m1r = m1n;

        float ps0 = 0.0f, ps1 = 0.0f;
        const int prow0 = (warp * 16 + grp) * PS_ST;
        const int prow1 = (warp * 16 + grp + 8) * PS_ST;
#pragma unroll
        for (int ni = 0; ni < 4; ++ni) {
            const int col = ni * 8 + 2 * tig;
            const float p00 = __expf(sf[ni][0] - m0n);
            const float p01 = __expf(sf[ni][1] - m0n);
            const float p10 = __expf(sf[ni][2] - m1n);
            const float p11 = __expf(sf[ni][3] - m1n);
            ps0 += p00 + p01;
            ps1 += p10 + p11;
            Ps[prow0 + col]     = f2tf32(p00);
            Ps[prow0 + col + 1] = f2tf32(p01);
            Ps[prow1 + col]     = f2tf32(p10);
            Ps[prow1 + col + 1] = f2tf32(p11);
        }
        ps0 += __shfl_xor_sync(0xffffffffu, ps0, 1);
        ps0 += __shfl_xor_sync(0xffffffffu, ps0, 2);
        ps1 += __shfl_xor_sync(0xffffffffu, ps1, 1);
        ps1 += __shfl_xor_sync(0xffffffffu, ps1, 2);
        l0r += ps0;
        l1r += ps1;

        __syncwarp();

#pragma unroll
        for (int k4 = 0; k4 < 4; ++k4) {
            const int kk = k4 * 8;
            const uint32_t a0 = Ps[prow0 + kk + tig];
            const uint32_t a1 = Ps[prow1 + kk + tig];
            const uint32_t a2 = Ps[prow0 + kk + tig + 4];
            const uint32_t a3 = Ps[prow1 + kk + tig + 4];
#pragma unroll
            for (int ni = 0; ni < 8; ++ni) {
                const int col = ni * 8 + grp;
                const uint32_t b0 = Vs[(kk + tig)     * VS_ST + col];
                const uint32_t b1 = Vs[(kk + tig + 4) * VS_ST + col];
                mma_tf32(o[ni][0], o[ni][1], o[ni][2], o[ni][3],
                         a0, a1, a2, a3, b0, b1);
            }
        }
    }

    const float inv0 = 1.0f / l0r;
    const float inv1 = 1.0f / l1r;
    const int b = bh / HEADS;
    const int h = bh % HEADS;
    const size_t r0 = ((size_t)b * SEQ + (q0 + grp))     * EMB + h * HDIM;
    const size_t r1 = ((size_t)b * SEQ + (q0 + grp + 8)) * EMB + h * HDIM;
#pragma unroll
    for (int ni = 0; ni < 8; ++ni) {
        const int col = ni * 8 + 2 * tig;
        float2 w0, w1;
        w0.x = o[ni][0] * inv0;
        w0.y = o[ni][1] * inv0;
        w1.x = o[ni][2] * inv1;
        w1.y = o[ni][3] * inv1;
        *(float2*)(g_att + r0 + col) = w0;
        *(float2*)(g_att + r1 + col) = w1;
    }
}

// ================= output projection, FMA2, smem-free (PROVEN R8, verbatim) =================
__global__ __launch_bounds__(256) void proj_m8c4_f2_kernel(
    const float* __restrict__ Wp,
    const float* __restrict__ bp,
    float* __restrict__ out)
{
    const int idx = blockIdx.x * 256 + threadIdx.x;
    const int mg  = idx / 192;
    const int c4  = idx % 192;
    const int m0  = mg * 8;
    const int c0  = c4 * 4;

    const float* ar = g_att + (size_t)m0 * EMB;

    u64t acc2[8][2];
#pragma unroll
    for (int i = 0; i < 8; ++i) { acc2[i][0] = 0ull; acc2[i][1] = 0ull; }

#pragma unroll 2
    for (int k4 = 0; k4 < EMB; k4 += 4) {
        const ulonglong2 wv0 = *(const ulonglong2*)&Wp[(size_t)(k4 + 0) * EMB + c0];
        const ulonglong2 wv1 = *(const ulonglong2*)&Wp[(size_t)(k4 + 1) * EMB + c0];
        const ulonglong2 wv2 = *(const ulonglong2*)&Wp[(size_t)(k4 + 2) * EMB + c0];
        const ulonglong2 wv3 = *(const ulonglong2*)&Wp[(size_t)(k4 + 3) * EMB + c0];

#pragma unroll
        for (int i = 0; i < 8; ++i) {
            const float4 av = *(const float4*)&ar[(size_t)i * EMB + k4];
            const u64t a0 = pack2(av.x, av.x);
            const u64t a1 = pack2(av.y, av.y);
            const u64t a2 = pack2(av.z, av.z);
            const u64t a3 = pack2(av.w, av.w);
            acc2[i][0] = fma2(a0, wv0.x, acc2[i][0]);
            acc2[i][1] = fma2(a0, wv0.y, acc2[i][1]);
            acc2[i][0] = fma2(a1, wv1.x, acc2[i][0]);
            acc2[i][1] = fma2(a1, wv1.y, acc2[i][1]);
            acc2[i][0] = fma2(a2, wv2.x, acc2[i][0]);
            acc2[i][1] = fma2(a2, wv2.y, acc2[i][1]);
            acc2[i][0] = fma2(a3, wv3.x, acc2[i][0]);
            acc2[i][1] = fma2(a3, wv3.y, acc2[i][1]);
        }
    }

#pragma unroll
    for (int i = 0; i < 8; ++i) {
        const int m = m0 + i;
        float a[4];
        unpack2(acc2[i][0], a[0], a[1]);
        unpack2(acc2[i][1], a[2], a[3]);
        float4 r;
        r.x = a[0] + bp[c0 + 0];
        r.y = a[1] + bp[c0 + 1];
        r.z = a[2] + bp[c0 + 2];
        r.w = a[3] + bp[c0 + 3];
        *(float4*)(out + (size_t)m * EMB + c0) = r;
    }
}

// ================= launch =================
extern "C" void kernel_launch(void* const* d_in, const int* in_sizes, int n_in,
                              void* d_out, int out_size)
{
    const float *x = nullptr, *Wqkv = nullptr, *bqkv = nullptr,
                *Wproj = nullptr, *bproj = nullptr;
    for (int i = 0; i < n_in; ++i) {
        switch (in_sizes[i]) {
            case 6291456: x     = (const float*)d_in[i]; break;
            case 1769472: Wqkv  = (const float*)d_in[i]; break;
            case 2304:    bqkv  = (const float*)d_in[i]; break;
            case 589824:  Wproj = (const float*)d_in[i]; break;
            case 768:     bproj = (const float*)d_in[i]; break;
            default: break;
        }
    }
    float* out = (float*)d_out;

    qkv_tf32_kernel<<<2304, 256>>>(x, Wqkv, bqkv);
    attn_tf32_kernel<<<768, 256>>>();
    proj_m8c4_f2_kernel<<<768, 256>>>(Wproj, bproj, out);

    (void)out_size;
}

// round 15
// speedup vs baseline: 6.8941x; 1.2174x over previous
#include <cuda_runtime.h>
#include <math.h>
#include <stdint.h>

#define EMB   768
#define NQKV  2304
#define BATCH 4
#define SEQ   2048
#define HEADS 12
#define HDIM  64
#define MTOK  (BATCH*SEQ)     // 8192
#define BH    (BATCH*HEADS)   // 48
#define ATT_SCALE 0.03608439182435161f   // 1/sqrt(768)

typedef unsigned long long u64t;

// ---- packed f32x2 helpers (proven R8) ----
__device__ __forceinline__ u64t pack2(float lo, float hi) {
    u64t r;
    asm("mov.b64 %0, {%1, %2};" : "=l"(r) : "f"(lo), "f"(hi));
    return r;
}
__device__ __forceinline__ void unpack2(u64t v, float& lo, float& hi) {
    asm("mov.b64 {%0, %1}, %2;" : "=f"(lo), "=f"(hi) : "l"(v));
}
__device__ __forceinline__ u64t fma2(u64t a, u64t b, u64t c) {
    u64t r;
    asm("fma.rn.f32x2 %0, %1, %2, %3;" : "=l"(r) : "l"(a), "l"(b), "l"(c));
    return r;
}

// ---- tf32 helpers ----
__device__ __forceinline__ uint32_t f2tf32(float f) {
    uint32_t r;
    asm("cvt.rna.tf32.f32 %0, %1;" : "=r"(r) : "f"(f));
    return r;
}
__device__ __forceinline__ void mma_tf32(
    float& c0, float& c1, float& c2, float& c3,
    uint32_t a0, uint32_t a1, uint32_t a2, uint32_t a3,
    uint32_t b0, uint32_t b1)
{
    asm volatile(
        "mma.sync.aligned.m16n8k8.row.col.f32.tf32.tf32.f32 "
        "{%0,%1,%2,%3}, {%4,%5,%6,%7}, {%8,%9}, {%0,%1,%2,%3};"
        : "+f"(c0), "+f"(c1), "+f"(c2), "+f"(c3)
        : "r"(a0), "r"(a1), "r"(a2), "r"(a3), "r"(b0), "r"(b1));
}

// ---------------- device scratch ----------------
__device__ __align__(16) float g_q[(size_t)BH * SEQ * HDIM];
__device__ __align__(16) float g_k[(size_t)BH * SEQ * HDIM];
__device__ __align__(16) float g_v[(size_t)BH * SEQ * HDIM];
__device__ __align__(16) float g_att[(size_t)MTOK * EMB];   // [b*n, h*64+d]

// ================= QKV GEMM: tf32 mma, 1-D grid + register prefetch =================
// PROVEN R14 structure (BS_STRIDE=136 conflict-free); added: next-tile A/B prefetch.
#define AS_STRIDE 20
#define BS_STRIDE 136
__global__ __launch_bounds__(256) void qkv_tf32_kernel(
    const float* __restrict__ A,     // x [8192, 768]
    const float* __restrict__ B,     // W_qkv [768, 2304]
    const float* __restrict__ bias)  // b_qkv [2304]
{
    __shared__ uint32_t As[64 * AS_STRIDE];
    __shared__ uint32_t Bs[16 * BS_STRIDE];

    const int tid  = threadIdx.x;
    const int bm   = blockIdx.x / 18;
    const int bn   = blockIdx.x % 18;
    const int row0 = bm * 64;
    const int col0 = bn * 128;

    const int warp = tid >> 5;
    const int lane = tid & 31;
    const int wm   = warp >> 2;
    const int wn   = warp & 3;
    const int grp  = lane >> 2;
    const int tig  = lane & 3;

    const int a_row = tid >> 2;
    const int a_kc  = (tid & 3) << 2;
    const int br0 = tid >> 5;
    const int bc0 = (tid & 31) << 2;
    const int br1 = br0 + 8;

    float acc[2][4][4];
#pragma unroll
    for (int mi = 0; mi < 2; ++mi)
#pragma unroll
        for (int ni = 0; ni < 4; ++ni)
#pragma unroll
            for (int r = 0; r < 4; ++r) acc[mi][ni][r] = 0.0f;

    // prefetch k-tile 0
    float4 av  = *(const float4*)&A[(size_t)(row0 + a_row) * EMB + a_kc];
    float4 bv0 = *(const float4*)&B[(size_t)br0 * NQKV + col0 + bc0];
    float4 bv1 = *(const float4*)&B[(size_t)br1 * NQKV + col0 + bc0];

    for (int k0 = 0; k0 < EMB; k0 += 16) {
        __syncthreads();
        As[a_row * AS_STRIDE + a_kc + 0] = f2tf32(av.x);
        As[a_row * AS_STRIDE + a_kc + 1] = f2tf32(av.y);
        As[a_row * AS_STRIDE + a_kc + 2] = f2tf32(av.z);
        As[a_row * AS_STRIDE + a_kc + 3] = f2tf32(av.w);
        Bs[br0 * BS_STRIDE + bc0 + 0] = f2tf32(bv0.x);
        Bs[br0 * BS_STRIDE + bc0 + 1] = f2tf32(bv0.y);
        Bs[br0 * BS_STRIDE + bc0 + 2] = f2tf32(bv0.z);
        Bs[br0 * BS_STRIDE + bc0 + 3] = f2tf32(bv0.w);
        Bs[br1 * BS_STRIDE + bc0 + 0] = f2tf32(bv1.x);
        Bs[br1 * BS_STRIDE + bc0 + 1] = f2tf32(bv1.y);
        Bs[br1 * BS_STRIDE + bc0 + 2] = f2tf32(bv1.z);
        Bs[br1 * BS_STRIDE + bc0 + 3] = f2tf32(bv1.w);
        __syncthreads();

        // prefetch next k-tile (overlaps with mma below)
        if (k0 + 16 < EMB) {
            av  = *(const float4*)&A[(size_t)(row0 + a_row) * EMB + k0 + 16 + a_kc];
            bv0 = *(const float4*)&B[(size_t)(k0 + 16 + br0) * NQKV + col0 + bc0];
            bv1 = *(const float4*)&B[(size_t)(k0 + 16 + br1) * NQKV + col0 + bc0];
        }

#pragma unroll
        for (int ks = 0; ks < 2; ++ks) {
            const int kk = ks * 8;
            uint32_t afr[2][4];
#pragma unroll
            for (int mi = 0; mi < 2; ++mi) {
                const int rbase = wm * 32 + mi * 16 + grp;
                afr[mi][0] = As[(rbase)     * AS_STRIDE + kk + tig];
                afr[mi][1] = As[(rbase + 8) * AS_STRIDE + kk + tig];
                afr[mi][2] = As[(rbase)     * AS_STRIDE + kk + tig + 4];
                afr[mi][3] = As[(rbase + 8) * AS_STRIDE + kk + tig + 4];
            }
            uint32_t bfr[4][2];
#pragma unroll
            for (int ni = 0; ni < 4; ++ni) {
                const int col = wn * 32 + ni * 8 + grp;
                bfr[ni][0] = Bs[(kk + tig)     * BS_STRIDE + col];
                bfr[ni][1] = Bs[(kk + tig + 4) * BS_STRIDE + col];
            }
#pragma unroll
            for (int mi = 0; mi < 2; ++mi)
#pragma unroll
                for (int ni = 0; ni < 4; ++ni)
                    mma_tf32(acc[mi][ni][0], acc[mi][ni][1],
                             acc[mi][ni][2], acc[mi][ni][3],
                             afr[mi][0], afr[mi][1], afr[mi][2], afr[mi][3],
                             bfr[ni][0], bfr[ni][1]);
        }
    }

#pragma unroll
    for (int mi = 0; mi < 2; ++mi) {
        const int rA = row0 + wm * 32 + mi * 16 + grp;
#pragma unroll
        for (int ni = 0; ni < 4; ++ni) {
            const int cA = col0 + wn * 32 + ni * 8 + 2 * tig;
#pragma unroll
            for (int r = 0; r < 4; ++r) {
                const int m = rA + ((r >= 2) ? 8 : 0);
                const int c = cA + (r & 1);
                const float s = acc[mi][ni][r] + bias[c];
                const int which = c % 3;
                const int d     = (c / 3) % HDIM;
                const int h     = c / (HDIM * 3);
                const int b     = m / SEQ;
                const int n     = m % SEQ;
                float* dst = (which == 0) ? g_q : ((which == 1) ? g_k : g_v);
                dst[(((size_t)b * HEADS + h) * SEQ + n) * HDIM + d] = s;
            }
        }
    }
}

// ================= flash attention: tf32 mma, natural-K layout, conflict-free =================
// Changes vs PROVEN R13/R14:
//   (a) K stored NATURAL [key][d] stride 68 (mma row.col B is [n][k] = K natural).
//       Loads: bank = 4*grp+tig+kk -> all 32 lanes distinct. Stores: uint4, conflict-free.
//   (b) VS_ST 68 -> 72: V B-frag bank = 8*tig+grp -> all distinct.
#define KN_ST 68
#define VS_ST 72
#define PS_ST 36
__global__ __launch_bounds__(256, 2) void attn_tf32_kernel()
{
    __shared__ uint32_t Kn[32 * KN_ST];    // [key][d]  8.5 KB
    __shared__ uint32_t Vs[32 * VS_ST];    // [key][d]  9.0 KB
    __shared__ uint32_t Ps[128 * PS_ST];   // [q][key] 18.4 KB

    const int bx   = blockIdx.x;
    const int bh   = bx >> 4;
    const int qt   = bx & 15;
    const int tid  = threadIdx.x;
    const int warp = tid >> 5;
    const int lane = tid & 31;
    const int grp  = lane >> 2;
    const int tig  = lane & 3;
    const int q0   = qt * 128 + warp * 16;

    const float* Qb = g_q + (size_t)bh * SEQ * HDIM;
    const float* Kb = g_k + (size_t)bh * SEQ * HDIM;
    const float* Vb = g_v + (size_t)bh * SEQ * HDIM;

    const int st_key0 = tid >> 4;              // 0..15
    const int st_key1 = (tid + 256) >> 4;      // 16..31
    const int st_d    = (tid & 15) << 2;       // 0..60

    uint32_t qf[8][4];
#pragma unroll
    for (int k8 = 0; k8 < 8; ++k8) {
        const int d0 = k8 * 8;
        qf[k8][0] = f2tf32(Qb[(size_t)(q0 + grp)     * HDIM + d0 + tig]     * ATT_SCALE);
        qf[k8][1] = f2tf32(Qb[(size_t)(q0 + grp + 8) * HDIM + d0 + tig]     * ATT_SCALE);
        qf[k8][2] = f2tf32(Qb[(size_t)(q0 + grp)     * HDIM + d0 + tig + 4] * ATT_SCALE);
        qf[k8][3] = f2tf32(Qb[(size_t)(q0 + grp + 8) * HDIM + d0 + tig + 4] * ATT_SCALE);
    }

    float o[8][4];
#pragma unroll
    for (int ni = 0; ni < 8; ++ni)
#pragma unroll
        for (int r = 0; r < 4; ++r) o[ni][r] = 0.0f;
    float m0r = -1e30f, m1r = -1e30f, l0r = 0.0f, l1r = 0.0f;

    float4 kpre0 = *(const float4*)&Kb[(size_t)st_key0 * HDIM + st_d];
    float4 kpre1 = *(const float4*)&Kb[(size_t)st_key1 * HDIM + st_d];
    float4 vpre0 = *(const float4*)&Vb[(size_t)st_key0 * HDIM + st_d];
    float4 vpre1 = *(const float4*)&Vb[(size_t)st_key1 * HDIM + st_d];

    for (int kt = 0; kt < SEQ / 32; ++kt) {
        __syncthreads();
        {
            uint4 kt0, kt1, vt0, vt1;
            kt0.x = f2tf32(kpre0.x);
            kt0.y = f2tf32(kpre0.y);
            kt0.z = f2tf32(kpre0.z);
            kt0.w = f2tf32(kpre0.w);
            kt1.x = f2tf32(kpre1.x);
            kt1.y = f2tf32(kpre1.y);
            kt1.z = f2tf32(kpre1.z);
            kt1.w = f2tf32(kpre1.w);
            vt0.x = f2tf32(vpre0.x);
            vt0.y = f2tf32(vpre0.y);
            vt0.z = f2tf32(vpre0.z);
            vt0.w = f2tf32(vpre0.w);
            vt1.x = f2tf32(vpre1.x);
            vt1.y = f2tf32(vpre1.y);
            vt1.z = f2tf32(vpre1.z);
            vt1.w = f2tf32(vpre1.w);
            *(uint4*)&Kn[st_key0 * KN_ST + st_d] = kt0;
            *(uint4*)&Kn[st_key1 * KN_ST + st_d] = kt1;
            *(uint4*)&Vs[st_key0 * VS_ST + st_d] = vt0;
            *(uint4*)&Vs[st_key1 * VS_ST + st_d] = vt1;
        }
        __syncthreads();

        if (kt + 1 < SEQ / 32) {
            const size_t base = (size_t)(kt + 1) * 32 * HDIM;
            kpre0 = *(const float4*)&Kb[base + (size_t)st_key0 * HDIM + st_d];
            kpre1 = *(const float4*)&Kb[base + (size_t)st_key1 * HDIM + st_d];
            vpre0 = *(const float4*)&Vb[base + (size_t)st_key0 * HDIM + st_d];
            vpre1 = *(const float4*)&Vb[base + (size_t)st_key1 * HDIM + st_d];
        }

        // ---- S = Q*K^T : B-frag b0 = K[col][kk+tig] (natural layout) ----
        float sf[4][4];
#pragma unroll
        for (int ni = 0; ni < 4; ++ni)
#pragma unroll
            for (int r = 0; r < 4; ++r) sf[ni][r] = 0.0f;
#pragma unroll
        for (int k8 = 0; k8 < 8; ++k8) {
            const int kk = k8 * 8;
#pragma unroll
            for (int ni = 0; ni < 4; ++ni) {
                const int col = ni * 8 + grp;
                const uint32_t b0 = Kn[col * KN_ST + kk + tig];
                const uint32_t b1 = Kn[col * KN_ST + kk + tig + 4];
                mma_tf32(sf[ni][0], sf[ni][1], sf[ni][2], sf[ni][3],
                         qf[k8][0], qf[k8][1], qf[k8][2], qf[k8][3], b0, b1);
            }
        }

        // ---- online softmax ----
        float mx0 = -1e30f, mx1 = -1e30f;
#pragma unroll
        for (int ni = 0; ni < 4; ++ni) {
            mx0 = fmaxf(mx0, fmaxf(sf[ni][0], sf[ni][1]));
            mx1 = fmaxf(mx1, fmaxf(sf[ni][2], sf[ni][3]));
        }
        mx0 = fmaxf(mx0, __shfl_xor_sync(0xffffffffu, mx0, 1));
        mx0 = fmaxf(mx0, __shfl_xor_sync(0xffffffffu, mx0, 2));
        mx1 = fmaxf(mx1, __shfl_xor_sync(0xffffffffu, mx1, 1));
        mx1 = fmaxf(mx1, __shfl_xor_sync(0xffffffffu, mx1, 2));

        const float m0n = fmaxf(m0r, mx0);
        const float m1n = fmaxf(m1r, mx1);
        const float c0 = __expf(m0r - m0n);
        const float c1 = __expf(m1r - m1n);
        l0r *= c0;
        l1r *= c1;
#pragma unroll
        for (int ni = 0; ni < 8; ++ni) {
            o[ni][0] *= c0;
            o[ni][1] *= c0;
            o[ni][2] *= c1;
            o[ni][3] *= c1;
        }
        m0r = m0n;
        m1r = m1n;

        float ps0 = 0.0f, ps1 = 0.0f;
        const int prow0 = (warp * 16 + grp) * PS_ST;
        const int prow1 = (warp * 16 + grp + 8) * PS_ST;
#pragma unroll
        for (int ni = 0; ni < 4; ++ni) {
            const int col = ni * 8 + 2 * tig;
            const float p00 = __expf(sf[ni][0] - m0n);
            const float p01 = __expf(sf[ni][1] - m0n);
            const float p10 = __expf(sf[ni][2] - m1n);
            const float p11 = __expf(sf[ni][3] - m1n);
            ps0 += p00 + p01;
            ps1 += p10 + p11;
            Ps[prow0 + col]     = f2tf32(p00);
            Ps[prow0 + col + 1] = f2tf32(p01);
            Ps[prow1 + col]     = f2tf32(p10);
            Ps[prow1 + col + 1] = f2tf32(p11);
        }
        ps0 += __shfl_xor_sync(0xffffffffu, ps0, 1);
        ps0 += __shfl_xor_sync(0xffffffffu, ps0, 2);
        ps1 += __shfl_xor_sync(0xffffffffu, ps1, 1);
        ps1 += __shfl_xor_sync(0xffffffffu, ps1, 2);
        l0r += ps0;
        l1r += ps1;

        __syncwarp();

        // ---- O += P*V ----
#pragma unroll
        for (int k4 = 0; k4 < 4; ++k4) {
            const int kk = k4 * 8;
            const uint32_t a0 = Ps[prow0 + kk + tig];
            const uint32_t a1 = Ps[prow1 + kk + tig];
            const uint32_t a2 = Ps[prow0 + kk + tig + 4];
            const uint32_t a3 = Ps[prow1 + kk + tig + 4];
#pragma unroll
            for (int ni = 0; ni < 8; ++ni) {
                const int col = ni * 8 + grp;
                const uint32_t b0 = Vs[(kk + tig)     * VS_ST + col];
                const uint32_t b1 = Vs[(kk + tig + 4) * VS_ST + col];
                mma_tf32(o[ni][0], o[ni][1], o[ni][2], o[ni][3],
                         a0, a1, a2, a3, b0, b1);
            }
        }
    }

    const float inv0 = 1.0f / l0r;
    const float inv1 = 1.0f / l1r;
    const int b = bh / HEADS;
    const int h = bh % HEADS;
    const size_t r0 = ((size_t)b * SEQ + (q0 + grp))     * EMB + h * HDIM;
    const size_t r1 = ((size_t)b * SEQ + (q0 + grp + 8)) * EMB + h * HDIM;
#pragma unroll
    for (int ni = 0; ni < 8; ++ni) {
        const int col = ni * 8 + 2 * tig;
        float2 w0, w1;
        w0.x = o[ni][0] * inv0;
        w0.y = o[ni][1] * inv0;
        w1.x = o[ni][2] * inv1;
        w1.y = o[ni][3] * inv1;
        *(float2*)(g_att + r0 + col) = w0;
        *(float2*)(g_att + r1 + col) = w1;
    }
}

// ================= output projection, FMA2, smem-free (PROVEN R8, verbatim) =================
__global__ __launch_bounds__(256) void proj_m8c4_f2_kernel(
    const float* __restrict__ Wp,
    const float* __restrict__ bp,
    float* __restrict__ out)
{
    const int idx = blockIdx.x * 256 + threadIdx.x;
    const int mg  = idx / 192;
    const int c4  = idx % 192;
    const int m0  = mg * 8;
    const int c0  = c4 * 4;

    const float* ar = g_att + (size_t)m0 * EMB;

    u64t acc2[8][2];
#pragma unroll
    for (int i = 0; i < 8; ++i) { acc2[i][0] = 0ull; acc2[i][1] = 0ull; }

#pragma unroll 2
    for (int k4 = 0; k4 < EMB; k4 += 4) {
        const ulonglong2 wv0 = *(const ulonglong2*)&Wp[(size_t)(k4 + 0) * EMB + c0];
        const ulonglong2 wv1 = *(const ulonglong2*)&Wp[(size_t)(k4 + 1) * EMB + c0];
        const ulonglong2 wv2 = *(const ulonglong2*)&Wp[(size_t)(k4 + 2) * EMB + c0];
        const ulonglong2 wv3 = *(const ulonglong2*)&Wp[(size_t)(k4 + 3) * EMB + c0];

#pragma unroll
        for (int i = 0; i < 8; ++i) {
            const float4 av = *(const float4*)&ar[(size_t)i * EMB + k4];
            const u64t a0 = pack2(av.x, av.x);
            const u64t a1 = pack2(av.y, av.y);
            const u64t a2 = pack2(av.z, av.z);
            const u64t a3 = pack2(av.w, av.w);
            acc2[i][0] = fma2(a0, wv0.x, acc2[i][0]);
            acc2[i][1] = fma2(a0, wv0.y, acc2[i][1]);
            acc2[i][0] = fma2(a1, wv1.x, acc2[i][0]);
            acc2[i][1] = fma2(a1, wv1.y, acc2[i][1]);
            acc2[i][0] = fma2(a2, wv2.x, acc2[i][0]);
            acc2[i][1] = fma2(a2, wv2.y, acc2[i][1]);
            acc2[i][0] = fma2(a3, wv3.x, acc2[i][0]);
            acc2[i][1] = fma2(a3, wv3.y, acc2[i][1]);
        }
    }

#pragma unroll
    for (int i = 0; i < 8; ++i) {
        const int m = m0 + i;
        float a[4];
        unpack2(acc2[i][0], a[0], a[1]);
        unpack2(acc2[i][1], a[2], a[3]);
        float4 r;
        r.x = a[0] + bp[c0 + 0];
        r.y = a[1] + bp[c0 + 1];
        r.z = a[2] + bp[c0 + 2];
        r.w = a[3] + bp[c0 + 3];
        *(float4*)(out + (size_t)m * EMB + c0) = r;
    }
}

// ================= launch =================
extern "C" void kernel_launch(void* const* d_in, const int* in_sizes, int n_in,
                              void* d_out, int out_size)
{
    const float *x = nullptr, *Wqkv = nullptr, *bqkv = nullptr,
                *Wproj = nullptr, *bproj = nullptr;
    for (int i = 0; i < n_in; ++i) {
        switch (in_sizes[i]) {
            case 6291456: x     = (const float*)d_in[i]; break;
            case 1769472: Wqkv  = (const float*)d_in[i]; break;
            case 2304:    bqkv  = (const float*)d_in[i]; break;
            case 589824:  Wproj = (const float*)d_in[i]; break;
            case 768:     bproj = (const float*)d_in[i]; break;
            default: break;
        }
    }
    float* out = (float*)d_out;

    qkv_tf32_kernel<<<2304, 256>>>(x, Wqkv, bqkv);
    attn_tf32_kernel<<<768, 256>>>();
    proj_m8c4_f2_kernel<<<768, 256>>>(Wproj, bproj, out);

    (void)out_size;
}

// round 17
// speedup vs baseline: 7.5671x; 1.0976x over previous
#include <cuda_runtime.h>
#include <math.h>
#include <stdint.h>

#define EMB   768
#define NQKV  2304
#define BATCH 4
#define SEQ   2048
#define HEADS 12
#define HDIM  64
#define MTOK  (BATCH*SEQ)     // 8192
#define BH    (BATCH*HEADS)   // 48
#define ATT_SCALE 0.03608439182435161f   // 1/sqrt(768)

// ---- tf32 helpers ----
__device__ __forceinline__ uint32_t f2tf32(float f) {
    uint32_t r;
    asm("cvt.rna.tf32.f32 %0, %1;" : "=r"(r) : "f"(f));
    return r;
}
__device__ __forceinline__ void mma_tf32(
    float& c0, float& c1, float& c2, float& c3,
    uint32_t a0, uint32_t a1, uint32_t a2, uint32_t a3,
    uint32_t b0, uint32_t b1)
{
    asm volatile(
        "mma.sync.aligned.m16n8k8.row.col.f32.tf32.tf32.f32 "
        "{%0,%1,%2,%3}, {%4,%5,%6,%7}, {%8,%9}, {%0,%1,%2,%3};"
        : "+f"(c0), "+f"(c1), "+f"(c2), "+f"(c3)
        : "r"(a0), "r"(a1), "r"(a2), "r"(a3), "r"(b0), "r"(b1));
}

// ---------------- device scratch ----------------
__device__ __align__(16) float g_q[(size_t)BH * SEQ * HDIM];
__device__ __align__(16) float g_k[(size_t)BH * SEQ * HDIM];
__device__ __align__(16) float g_v[(size_t)BH * SEQ * HDIM];
__device__ __align__(16) float g_att[(size_t)MTOK * EMB];   // [b*n, h*64+d]

// ================= QKV GEMM: tf32 mma (PROVEN R15, verbatim) =================
#define AS_STRIDE 20
#define BS_STRIDE 136
__global__ __launch_bounds__(256) void qkv_tf32_kernel(
    const float* __restrict__ A,     // x [8192, 768]
    const float* __restrict__ B,     // W_qkv [768, 2304]
    const float* __restrict__ bias)  // b_qkv [2304]
{
    __shared__ uint32_t As[64 * AS_STRIDE];
    __shared__ uint32_t Bs[16 * BS_STRIDE];

    const int tid  = threadIdx.x;
    const int bm   = blockIdx.x / 18;
    const int bn   = blockIdx.x % 18;
    const int row0 = bm * 64;
    const int col0 = bn * 128;

    const int warp = tid >> 5;
    const int lane = tid & 31;
    const int wm   = warp >> 2;
    const int wn   = warp & 3;
    const int grp  = lane >> 2;
    const int tig  = lane & 3;

    const int a_row = tid >> 2;
    const int a_kc  = (tid & 3) << 2;
    const int br0 = tid >> 5;
    const int bc0 = (tid & 31) << 2;
    const int br1 = br0 + 8;

    float acc[2][4][4];
#pragma unroll
    for (int mi = 0; mi < 2; ++mi)
#pragma unroll
        for (int ni = 0; ni < 4; ++ni)
#pragma unroll
            for (int r = 0; r < 4; ++r) acc[mi][ni][r] = 0.0f;

    float4 av  = *(const float4*)&A[(size_t)(row0 + a_row) * EMB + a_kc];
    float4 bv0 = *(const float4*)&B[(size_t)br0 * NQKV + col0 + bc0];
    float4 bv1 = *(const float4*)&B[(size_t)br1 * NQKV + col0 + bc0];

    for (int k0 = 0; k0 < EMB; k0 += 16) {
        __syncthreads();
        As[a_row * AS_STRIDE + a_kc + 0] = f2tf32(av.x);
        As[a_row * AS_STRIDE + a_kc + 1] = f2tf32(av.y);
        As[a_row * AS_STRIDE + a_kc + 2] = f2tf32(av.z);
        As[a_row * AS_STRIDE + a_kc + 3] = f2tf32(av.w);
        Bs[br0 * BS_STRIDE + bc0 + 0] = f2tf32(bv0.x);
        Bs[br0 * BS_STRIDE + bc0 + 1] = f2tf32(bv0.y);
        Bs[br0 * BS_STRIDE + bc0 + 2] = f2tf32(bv0.z);
        Bs[br0 * BS_STRIDE + bc0 + 3] = f2tf32(bv0.w);
        Bs[br1 * BS_STRIDE + bc0 + 0] = f2tf32(bv1.x);
        Bs[br1 * BS_STRIDE + bc0 + 1] = f2tf32(bv1.y);
        Bs[br1 * BS_STRIDE + bc0 + 2] = f2tf32(bv1.z);
        Bs[br1 * BS_STRIDE + bc0 + 3] = f2tf32(bv1.w);
        __syncthreads();

        if (k0 + 16 < EMB) {
            av  = *(const float4*)&A[(size_t)(row0 + a_row) * EMB + k0 + 16 + a_kc];
            bv0 = *(const float4*)&B[(size_t)(k0 + 16 + br0) * NQKV + col0 + bc0];
            bv1 = *(const float4*)&B[(size_t)(k0 + 16 + br1) * NQKV + col0 + bc0];
        }

#pragma unroll
        for (int ks = 0; ks < 2; ++ks) {
            const int kk = ks * 8;
            uint32_t afr[2][4];
#pragma unroll
            for (int mi = 0; mi < 2; ++mi) {
                const int rbase = wm * 32 + mi * 16 + grp;
                afr[mi][0] = As[(rbase)     * AS_STRIDE + kk + tig];
                afr[mi][1] = As[(rbase + 8) * AS_STRIDE + kk + tig];
                afr[mi][2] = As[(rbase)     * AS_STRIDE + kk + tig + 4];
                afr[mi][3] = As[(rbase + 8) * AS_STRIDE + kk + tig + 4];
            }
            uint32_t bfr[4][2];
#pragma unroll
            for (int ni = 0; ni < 4; ++ni) {
                const int col = wn * 32 + ni * 8 + grp;
                bfr[ni][0] = Bs[(kk + tig)     * BS_STRIDE + col];
                bfr[ni][1] = Bs[(kk + tig + 4) * BS_STRIDE + col];
            }
#pragma unroll
            for (int mi = 0; mi < 2; ++mi)
#pragma unroll
                for (int ni = 0; ni < 4; ++ni)
                    mma_tf32(acc[mi][ni][0], acc[mi][ni][1],
                             acc[mi][ni][2], acc[mi][ni][3],
                             afr[mi][0], afr[mi][1], afr[mi][2], afr[mi][3],
                             bfr[ni][0], bfr[ni][1]);
        }
    }

#pragma unroll
    for (int mi = 0; mi < 2; ++mi) {
        const int rA = row0 + wm * 32 + mi * 16 + grp;
#pragma unroll
        for (int ni = 0; ni < 4; ++ni) {
            const int cA = col0 + wn * 32 + ni * 8 + 2 * tig;
#pragma unroll
            for (int r = 0; r < 4; ++r) {
                const int m = rA + ((r >= 2) ? 8 : 0);
                const int c = cA + (r & 1);
                const float s = acc[mi][ni][r] + bias[c];
                const int which = c % 3;
                const int d     = (c / 3) % HDIM;
                const int h     = c / (HDIM * 3);
                const int b     = m / SEQ;
                const int n     = m % SEQ;
                float* dst = (which == 0) ? g_q : ((which == 1) ? g_k : g_v);
                dst[(((size_t)b * HEADS + h) * SEQ + n) * HDIM + d] = s;
            }
        }
    }
}

// ================= flash attention: tf32 mma (PROVEN R15, verbatim) =================
#define KN_ST 68
#define VS_ST 72
#define PS_ST 36
__global__ __launch_bounds__(256, 2) void attn_tf32_kernel()
{
    __shared__ uint32_t Kn[32 * KN_ST];
    __shared__ uint32_t Vs[32 * VS_ST];
    __shared__ uint32_t Ps[128 * PS_ST];

    const int bx   = blockIdx.x;
    const int bh   = bx >> 4;
    const int qt   = bx & 15;
    const int tid  = threadIdx.x;
    const int warp = tid >> 5;
    const int lane = tid & 31;
    const int grp  = lane >> 2;
    const int tig  = lane & 3;
    const int q0   = qt * 128 + warp * 16;

    const float* Qb = g_q + (size_t)bh * SEQ * HDIM;
    const float* Kb = g_k + (size_t)bh * SEQ * HDIM;
    const float* Vb = g_v + (size_t)bh * SEQ * HDIM;

    const int st_key0 = tid >> 4;
    const int st_key1 = (tid + 256) >> 4;
    const int st_d    = (tid & 15) << 2;

    uint32_t qf[8][4];
#pragma unroll
    for (int k8 = 0; k8 < 8; ++k8) {
        const int d0 = k8 * 8;
        qf[k8][0] = f2tf32(Qb[(size_t)(q0 + grp)     * HDIM + d0 + tig]     * ATT_SCALE);
        qf[k8][1] = f2tf32(Qb[(size_t)(q0 + grp + 8) * HDIM + d0 + tig]     * ATT_SCALE);
        qf[k8][2] = f2tf32(Qb[(size_t)(q0 + grp)     * HDIM + d0 + tig + 4] * ATT_SCALE);
        qf[k8][3] = f2tf32(Qb[(size_t)(q0 + grp + 8) * HDIM + d0 + tig + 4] * ATT_SCALE);
    }

    float o[8][4];
#pragma unroll
    for (int ni = 0; ni < 8; ++ni)
#pragma unroll
        for (int r = 0; r < 4; ++r) o[ni][r] = 0.0f;
    float m0r = -1e30f, m1r = -1e30f, l0r = 0.0f, l1r = 0.0f;

    float4 kpre0 = *(const float4*)&Kb[(size_t)st_key0 * HDIM + st_d];
    float4 kpre1 = *(const float4*)&Kb[(size_t)st_key1 * HDIM + st_d];
    float4 vpre0 = *(const float4*)&Vb[(size_t)st_key0 * HDIM + st_d];
    float4 vpre1 = *(const float4*)&Vb[(size_t)st_key1 * HDIM + st_d];

    for (int kt = 0; kt < SEQ / 32; ++kt) {
        __syncthreads();
        {
            uint4 kt0, kt1, vt0, vt1;
            kt0.x = f2tf32(kpre0.x);
            kt0.y = f2tf32(kpre0.y);
            kt0.z = f2tf32(kpre0.z);
            kt0.w = f2tf32(kpre0.w);
            kt1.x = f2tf32(kpre1.x);
            kt1.y = f2tf32(kpre1.y);
            kt1.z = f2tf32(kpre1.z);
            kt1.w = f2tf32(kpre1.w);
            vt0.x = f2tf32(vpre0.x);
            vt0.y = f2tf32(vpre0.y);
            vt0.z = f2tf32(vpre0.z);
            vt0.w = f2tf32(vpre0.w);
            vt1.x = f2tf32(vpre1.x);
            vt1.y = f2tf32(vpre1.y);
            vt1.z = f2tf32(vpre1.z);
            vt1.w = f2tf32(vpre1.w);
            *(uint4*)&Kn[st_key0 * KN_ST + st_d] = kt0;
            *(uint4*)&Kn[st_key1 * KN_ST + st_d] = kt1;
            *(uint4*)&Vs[st_key0 * VS_ST + st_d] = vt0;
            *(uint4*)&Vs[st_key1 * VS_ST + st_d] = vt1;
        }
        __syncthreads();

        if (kt + 1 < SEQ / 32) {
            const size_t base = (size_t)(kt + 1) * 32 * HDIM;
            kpre0 = *(const float4*)&Kb[base + (size_t)st_key0 * HDIM + st_d];
            kpre1 = *(const float4*)&Kb[base + (size_t)st_key1 * HDIM + st_d];
            vpre0 = *(const float4*)&Vb[base + (size_t)st_key0 * HDIM + st_d];
            vpre1 = *(const float4*)&Vb[base + (size_t)st_key1 * HDIM + st_d];
        }

        float sf[4][4];
#pragma unroll
        for (int ni = 0; ni < 4; ++ni)
#pragma unroll
            for (int r = 0; r < 4; ++r) sf[ni][r] = 0.0f;
#pragma unroll
        for (int k8 = 0; k8 < 8; ++k8) {
            const int kk = k8 * 8;
#pragma unroll
            for (int ni = 0; ni < 4; ++ni) {
                const int col = ni * 8 + grp;
                const uint32_t b0 = Kn[col * KN_ST + kk + tig];
                const uint32_t b1 = Kn[col * KN_ST + kk + tig + 4];
                mma_tf32(sf[ni][0], sf[ni][1], sf[ni][2], sf[ni][3],
                         qf[k8][0], qf[k8][1], qf[k8][2], qf[k8][3], b0, b1);
            }
        }

        float mx0 = -1e30f, mx1 = -1e30f;
#pragma unroll
        for (int ni = 0; ni < 4; ++ni) {
            mx0 = fmaxf(mx0, fmaxf(sf[ni][0], sf[ni][1]));
            mx1 = fmaxf(mx1, fmaxf(sf[ni][2], sf[ni][3]));
        }
        mx0 = fmaxf(mx0, __shfl_xor_sync(0xffffffffu, mx0, 1));
        mx0 = fmaxf(mx0, __shfl_xor_sync(0xffffffffu, mx0, 2));
        mx1 = fmaxf(mx1, __shfl_xor_sync(0xffffffffu, mx1, 1));
        mx1 = fmaxf(mx1, __shfl_xor_sync(0xffffffffu, mx1, 2));

        const float m0n = fmaxf(m0r, mx0);
        const float m1n = fmaxf(m1r, mx1);
        const float c0 = __expf(m0r - m0n);
        const float c1 = __expf(m1r - m1n);
        l0r *= c0;
        l1r *= c1;
#pragma unroll
        for (int ni = 0; ni < 8; ++ni) {
            o[ni][0] *= c0;
            o[ni][1] *= c0;
            o[ni][2] *= c1;
            o[ni][3] *= c1;
        }
        m0r = m0n;
        m1r = m1n;

        float ps0 = 0.0f, ps1 = 0.0f;
        const int prow0 = (warp * 16 + grp) * PS_ST;
        const int prow1 = (warp * 16 + grp + 8) * PS_ST;
#pragma unroll
        for (int ni = 0; ni < 4; ++ni) {
            const int col = ni * 8 + 2 * tig;
            const float p00 = __expf(sf[ni][0] - m0n);
            const float p01 = __expf(sf[ni][1] - m0n);
            const float p10 = __expf(sf[ni][2] - m1n);
            const float p11 = __expf(sf[ni][3] - m1n);
            ps0 += p00 + p01;
            ps1 += p10 + p11;
            Ps[prow0 + col]     = f2tf32(p00);
            Ps[prow0 + col + 1] = f2tf32(p01);
            Ps[prow1 + col]     = f2tf32(p10);
            Ps[prow1 + col + 1] = f2tf32(p11);
        }
        ps0 += __shfl_xor_sync(0xffffffffu, ps0, 1);
        ps0 += __shfl_xor_sync(0xffffffffu, ps0, 2);
        ps1 += __shfl_xor_sync(0xffffffffu, ps1, 1);
        ps1 += __shfl_xor_sync(0xffffffffu, ps1, 2);
        l0r += ps0;
        l1r += ps1;

        __syncwarp();

#pragma unroll
        for (int k4 = 0; k4 < 4; ++k4) {
            const int kk = k4 * 8;
            const uint32_t a0 = Ps[prow0 + kk + tig];
            const uint32_t a1 = Ps[prow1 + kk + tig];
            const uint32_t a2 = Ps[prow0 + kk + tig + 4];
            const uint32_t a3 = Ps[prow1 + kk + tig + 4];
#pragma unroll
            for (int ni = 0; ni < 8; ++ni) {
                const int col = ni * 8 + grp;
                const uint32_t b0 = Vs[(kk + tig)     * VS_ST + col];
                const uint32_t b1 = Vs[(kk + tig + 4) * VS_ST + col];
                mma_tf32(o[ni][0], o[ni][1], o[ni][2], o[ni][3],
                         a0, a1, a2, a3, b0, b1);
            }
        }
    }

    const float inv0 = 1.0f / l0r;
    const float inv1 = 1.0f / l1r;
    const int b = bh / HEADS;
    const int h = bh % HEADS;
    const size_t r0 = ((size_t)b * SEQ + (q0 + grp))     * EMB + h * HDIM;
    const size_t r1 = ((size_t)b * SEQ + (q0 + grp + 8)) * EMB + h * HDIM;
#pragma unroll
    for (int ni = 0; ni < 8; ++ni) {
        const int col = ni * 8 + 2 * tig;
        float2 w0, w1;
        w0.x = o[ni][0] * inv0;
        w0.y = o[ni][1] * inv0;
        w1.x = o[ni][2] * inv1;
        w1.y = o[ni][3] * inv1;
        *(float2*)(g_att + r0 + col) = w0;
        *(float2*)(g_att + r1 + col) = w1;
    }
}

// ================= output projection: attention-style tf32 mma =================
// Structure copied from the (curse-exempt) attention kernel: A-fragments loaded
// DIRECTLY from gmem (g_att, like Q); only B (W_proj) is smem-staged, with the
// proven BS_STRIDE=136 conflict-free pattern + register prefetch. No A staging,
// no A-staging syncs. Epilogue writes d_out row-major + bias.
__global__ __launch_bounds__(256) void proj_attnstyle_tf32_kernel(
    const float* __restrict__ B,     // W_proj [768, 768]
    const float* __restrict__ bias,  // b_proj [768]
    float* __restrict__ out)
{
    __shared__ uint32_t Bs[16 * BS_STRIDE];

    const int tid  = threadIdx.x;
    const int bm   = blockIdx.x / 6;     // 0..127
    const int bn   = blockIdx.x % 6;     // 0..5
    const int row0 = bm * 64;
    const int col0 = bn * 128;

    const int warp = tid >> 5;
    const int lane = tid & 31;
    const int wm   = warp >> 2;          // 0..1
    const int wn   = warp & 3;           // 0..3
    const int grp  = lane >> 2;          // 0..7
    const int tig  = lane & 3;           // 0..3

    const int br0 = tid >> 5;            // 0..7
    const int bc0 = (tid & 31) << 2;     // 0..124
    const int br1 = br0 + 8;

    // per-warp A row bases (rows are fixed for the whole kernel)
    const size_t arow0 = (size_t)(row0 + wm * 32 + grp) * EMB;        // mi=0 row grp
    const size_t arow1 = arow0 + (size_t)8 * EMB;                     // mi=0 row grp+8
    const size_t arow2 = (size_t)(row0 + wm * 32 + 16 + grp) * EMB;   // mi=1 row grp
    const size_t arow3 = arow2 + (size_t)8 * EMB;                     // mi=1 row grp+8

    float acc[2][4][4];
#pragma unroll
    for (int mi = 0; mi < 2; ++mi)
#pragma unroll
        for (int ni = 0; ni < 4; ++ni)
#pragma unroll
            for (int r = 0; r < 4; ++r) acc[mi][ni][r] = 0.0f;

    float4 bv0 = *(const float4*)&B[(size_t)br0 * EMB + col0 + bc0];
    float4 bv1 = *(const float4*)&B[(size_t)br1 * EMB + col0 + bc0];

    for (int k0 = 0; k0 < EMB; k0 += 16) {
        __syncthreads();
        Bs[br0 * BS_STRIDE + bc0 + 0] = f2tf32(bv0.x);
        Bs[br0 * BS_STRIDE + bc0 + 1] = f2tf32(bv0.y);
        Bs[br0 * BS_STRIDE + bc0 + 2] = f2tf32(bv0.z);
        Bs[br0 * BS_STRIDE + bc0 + 3] = f2tf32(bv0.w);
        Bs[br1 * BS_STRIDE + bc0 + 0] = f2tf32(bv1.x);
        Bs[br1 * BS_STRIDE + bc0 + 1] = f2tf32(bv1.y);
        Bs[br1 * BS_STRIDE + bc0 + 2] = f2tf32(bv1.z);
        Bs[br1 * BS_STRIDE + bc0 + 3] = f2tf32(bv1.w);
        __syncthreads();

        if (k0 + 16 < EMB) {
            bv0 = *(const float4*)&B[(size_t)(k0 + 16 + br0) * EMB + col0 + bc0];
            bv1 = *(const float4*)&B[(size_t)(k0 + 16 + br1) * EMB + col0 + bc0];
        }

#pragma unroll
        for (int ks = 0; ks < 2; ++ks) {
            const int kk = k0 + ks * 8;
            // A fragments straight from gmem (attention-style, like Q loads)
            uint32_t afr[2][4];
            afr[0][0] = f2tf32(g_att[arow0 + kk + tig]);
            afr[0][1] = f2tf32(g_att[arow1 + kk + tig]);
            afr[0][2] = f2tf32(g_att[arow0 + kk + tig + 4]);
            afr[0][3] = f2tf32(g_att[arow1 + kk + tig + 4]);
            afr[1][0] = f2tf32(g_att[arow2 + kk + tig]);
            afr[1][1] = f2tf32(g_att[arow3 + kk + tig]);
            afr[1][2] = f2tf32(g_att[arow2 + kk + tig + 4]);
            afr[1][3] = f2tf32(g_att[arow3 + kk + tig + 4]);

            const int kks = ks * 8;
            uint32_t bfr[4][2];
#pragma unroll
            for (int ni = 0; ni < 4; ++ni) {
                const int col = wn * 32 + ni * 8 + grp;
                bfr[ni][0] = Bs[(kks + tig)     * BS_STRIDE + col];
                bfr[ni][1] = Bs[(kks + tig + 4) * BS_STRIDE + col];
            }
#pragma unroll
            for (int mi = 0; mi < 2; ++mi)
#pragma unroll
                for (int ni = 0; ni < 4; ++ni)
                    mma_tf32(acc[mi][ni][0], acc[mi][ni][1],
                             acc[mi][ni][2], acc[mi][ni][3],
                             afr[mi][0], afr[mi][1], afr[mi][2], afr[mi][3],
                             bfr[ni][0], bfr[ni][1]);
        }
    }

#pragma unroll
    for (int mi = 0; mi < 2; ++mi) {
        const int rA = row0 + wm * 32 + mi * 16 + grp;
#pragma unroll
        for (int ni = 0; ni < 4; ++ni) {
            const int cA = col0 + wn * 32 + ni * 8 + 2 * tig;
#pragma unroll
            for (int r = 0; r < 4; ++r) {
                const int m = rA + ((r >= 2) ? 8 : 0);
                const int c = cA + (r & 1);
                out[(size_t)m * EMB + c] = acc[mi][ni][r] + bias[c];
            }
        }
    }
}

// ================= launch =================
extern "C" void kernel_launch(void* const* d_in, const int* in_sizes, int n_in,
                              void* d_out, int out_size)
{
    const float *x = nullptr, *Wqkv = nullptr, *bqkv = nullptr,
                *Wproj = nullptr, *bproj = nullptr;
    for (int i = 0; i < n_in; ++i) {
        switch (in_sizes[i]) {
            case 6291456: x     = (const float*)d_in[i]; break;
            case 1769472: Wqkv  = (const float*)d_in[i]; break;
            case 2304:    bqkv  = (const float*)d_in[i]; break;
            case 589824:  Wproj = (const float*)d_in[i]; break;
            case 768:     bproj = (const float*)d_in[i]; break;
            default: break;
        }
    }
    float* out = (float*)d_out;

    qkv_tf32_kernel<<<2304, 256>>>(x, Wqkv, bqkv);
    attn_tf32_kernel<<<768, 256>>>();
    // attention-style proj: 128 M-tiles x 6 N-tiles = 768 blocks (1-D grid)
    proj_attnstyle_tf32_kernel<<<768, 256>>>(Wproj, bproj, out);

    (void)out_size;
}